// round 6
// baseline (speedup 1.0000x reference)
#include <cuda_runtime.h>
#include <cuda_bf16.h>
#include <math.h>
#include <stdint.h>

#define C_IN 256
#define NPOS 4096
#define NB   8
#define DQK  32
#define DV   256
#define BQ   128
#define BK   64
#define NCHUNK (NPOS / BK)       // 64
#define MBLKS  (NPOS / BQ)       // 32

#define QT_BYTES 16384           // 128 rows x 128B (32c hi | 32c lo per row)
#define KT_BYTES 8192            // 64 key-rows x 128B (hi | lo)
#define VT_BYTES 65536           // hi plane: 256 c-rows x 128B (64 keys), lo at +32768

__device__ unsigned char g_qt[NB * MBLKS * QT_BYTES];    // Q = g (wk proj)
__device__ unsigned char g_kt[NB * NCHUNK * KT_BYTES];   // K = f (wq proj)
__device__ unsigned char g_vt[NB * NCHUNK * VT_BYTES];   // V = h (wv proj), [c][key]

// ---------------- helpers ----------------
__device__ __forceinline__ uint32_t SW(uint32_t off) {   // SW128-style row swizzle
    return off ^ ((off >> 3) & 0x70);
}
__device__ __forceinline__ uint32_t smem_u32(const void* p) {
    uint32_t a;
    asm("{ .reg .u64 t; cvta.to.shared.u64 t, %1; cvt.u32.u64 %0, t; }" : "=r"(a) : "l"(p));
    return a;
}
__device__ __forceinline__ void split2(float a, float b, uint32_t& hi, uint32_t& lo) {
    __nv_bfloat16 ha = __float2bfloat16(a), hb = __float2bfloat16(b);
    __nv_bfloat162 hh; hh.x = ha; hh.y = hb;
    hi = *reinterpret_cast<uint32_t*>(&hh);
    __nv_bfloat162 ll;
    ll.x = __float2bfloat16(a - __bfloat162float(ha));
    ll.y = __float2bfloat16(b - __bfloat162float(hb));
    lo = *reinterpret_cast<uint32_t*>(&ll);
}
__device__ __forceinline__ unsigned long long pk2(float a, float b) {
    unsigned long long r;
    asm("mov.b64 %0, {%1,%2};" : "=l"(r) : "f"(a), "f"(b));
    return r;
}
__device__ __forceinline__ float2 up2(unsigned long long v) {
    float2 r;
    asm("mov.b64 {%0,%1}, %2;" : "=f"(r.x), "=f"(r.y) : "l"(v));
    return r;
}
__device__ __forceinline__ void fma2(unsigned long long &d, unsigned long long a, unsigned long long b) {
    asm("fma.rn.f32x2 %0, %1, %2, %0;" : "+l"(d) : "l"(a), "l"(b));
}
__device__ __forceinline__ void mbar_init(uint32_t mbar, uint32_t cnt) {
    asm volatile("mbarrier.init.shared.b64 [%0], %1;" :: "r"(mbar), "r"(cnt) : "memory");
}
__device__ __forceinline__ void mbar_expect(uint32_t mbar, uint32_t bytes) {
    asm volatile("mbarrier.arrive.expect_tx.shared.b64 _, [%0], %1;" :: "r"(mbar), "r"(bytes) : "memory");
}
__device__ __forceinline__ void mbar_arrive(uint32_t mbar) {
    asm volatile("mbarrier.arrive.shared.b64 _, [%0];" :: "r"(mbar) : "memory");
}
__device__ __forceinline__ void mbar_wait(uint32_t mbar, int phase) {
    asm volatile(
        "{\n\t.reg .pred P1;\n\t"
        "LAB_WAIT_%=:\n\t"
        "mbarrier.try_wait.parity.acquire.cta.shared::cta.b64 P1, [%0], %1, 0x989680;\n\t"
        "@P1 bra LAB_DONE_%=;\n\t"
        "bra LAB_WAIT_%=;\n\t"
        "LAB_DONE_%=:\n\t}"
        :: "r"(mbar), "r"((uint32_t)phase) : "memory");
}
__device__ __forceinline__ void bulk_g2s(uint32_t dst, const void* src, uint32_t bytes, uint32_t mbar) {
    asm volatile(
        "cp.async.bulk.shared::cluster.global.mbarrier::complete_tx::bytes [%0], [%1], %2, [%3];"
        :: "r"(dst), "l"(src), "r"(bytes), "r"(mbar) : "memory");
}
__device__ __forceinline__ void sts32(uint32_t a, uint32_t v) {
    asm volatile("st.shared.b32 [%0], %1;" :: "r"(a), "r"(v));
}
__device__ __forceinline__ void barsync(int id) {
    asm volatile("bar.sync %0, 64;" :: "r"(id) : "memory");
}
__device__ __forceinline__ void ldsm4(uint32_t& r0, uint32_t& r1, uint32_t& r2, uint32_t& r3,
                                      uint32_t addr) {
    asm volatile("ldmatrix.sync.aligned.m8n8.x4.shared.b16 {%0,%1,%2,%3}, [%4];"
                 : "=r"(r0), "=r"(r1), "=r"(r2), "=r"(r3) : "r"(addr));
}
__device__ __forceinline__ void mma16816(float* c, uint32_t a0, uint32_t a1, uint32_t a2, uint32_t a3,
                                         uint32_t b0, uint32_t b1) {
    asm volatile(
        "mma.sync.aligned.m16n8k16.row.col.f32.bf16.bf16.f32 "
        "{%0,%1,%2,%3}, {%4,%5,%6,%7}, {%8,%9}, {%0,%1,%2,%3};"
        : "+f"(c[0]), "+f"(c[1]), "+f"(c[2]), "+f"(c[3])
        : "r"(a0), "r"(a1), "r"(a2), "r"(a3), "r"(b0), "r"(b1));
}

// ============================================================================
// Fused projection: one pass over x computes all 320 output channels.
// ch 0..31 -> K tiles (wq/bq), 32..63 -> Q tiles (wk/bk), 64..319 -> V (wv/bv).
// ============================================================================
__global__ void proj_fused_kernel(const float* __restrict__ x,
                                  const float* __restrict__ wq, const float* __restrict__ bq,
                                  const float* __restrict__ wk, const float* __restrict__ bk,
                                  const float* __restrict__ wv, const float* __restrict__ bv,
                                  unsigned char* __restrict__ kt, unsigned char* __restrict__ qt,
                                  unsigned char* __restrict__ vt) {
    __shared__ float xs[32 * 64];        // 8KB
    __shared__ float ws[320 * 32];       // 40KB
    const int tid = threadIdx.x;
    const int tx = tid & 15, ty = tid >> 4;     // 16 n-quads x 16 ch-slabs(20 ch)
    const int b  = blockIdx.y;
    const int n0 = blockIdx.x * 64;

    unsigned long long acc[20][2];
#pragma unroll
    for (int j = 0; j < 20; j++) { acc[j][0] = 0ull; acc[j][1] = 0ull; }

    for (int cb = 0; cb < C_IN; cb += 32) {
        __syncthreads();
        for (int i = tid; i < 512; i += 256) {
            int cc = i >> 4, nq = i & 15;
            ((float4*)xs)[cc * 16 + nq] =
                *(const float4*)&x[((size_t)b * C_IN + cb + cc) * NPOS + n0 + nq * 4];
        }
        for (int i = tid; i < 2560; i += 256) {
            int row = i >> 3, c4 = i & 7;
            const float* src = (row < 32) ? (wq + row * C_IN)
                             : (row < 64) ? (wk + (row - 32) * C_IN)
                                          : (wv + (row - 64) * C_IN);
            ((float4*)ws)[i] = *(const float4*)(src + cb + c4 * 4);
        }
        __syncthreads();
#pragma unroll 2
        for (int cc = 0; cc < 32; cc++) {
            ulonglong2 xv = *(ulonglong2*)&xs[cc * 64 + tx * 4];
#pragma unroll
            for (int j = 0; j < 20; j++) {
                float wv_ = ws[(ty * 20 + j) * 32 + cc];
                unsigned long long wp = pk2(wv_, wv_);
                fma2(acc[j][0], xv.x, wp);
                fma2(acc[j][1], xv.y, wp);
            }
        }
    }

#pragma unroll
    for (int jp = 0; jp < 10; jp++) {
        const int co = ty * 20 + jp * 2;
        float a0[4], a1[4];
        { float2 t = up2(acc[jp * 2][0]);     a0[0] = t.x; a0[1] = t.y;
          t = up2(acc[jp * 2][1]);            a0[2] = t.x; a0[3] = t.y; }
        { float2 t = up2(acc[jp * 2 + 1][0]); a1[0] = t.x; a1[1] = t.y;
          t = up2(acc[jp * 2 + 1][1]);        a1[2] = t.x; a1[3] = t.y; }

        if (co < 64) {
            const bool isQ = co >= 32;
            const int c0 = co & 31;
            const float bb0 = isQ ? bk[c0] : bq[c0];
            const float bb1 = isQ ? bk[c0 + 1] : bq[c0 + 1];
            unsigned char* dst = isQ ? qt : kt;
#pragma unroll
            for (int r = 0; r < 4; r++) {
                int n = n0 + tx * 4 + r;
                uint32_t hi, lo;
                split2(a0[r] + bb0, a1[r] + bb1, hi, lo);
                size_t tb; uint32_t row;
                if (isQ) { tb = ((size_t)b * MBLKS  + (n >> 7)) * QT_BYTES; row = n & 127; }
                else     { tb = ((size_t)b * NCHUNK + (n >> 6)) * KT_BYTES; row = n & 63;  }
                *(uint32_t*)(dst + tb + SW(row * 128 + c0 * 2))      = hi;
                *(uint32_t*)(dst + tb + SW(row * 128 + 64 + c0 * 2)) = lo;
            }
        } else {
            const size_t tb = ((size_t)b * NCHUNK + (n0 >> 6)) * VT_BYTES;
#pragma unroll
            for (int h = 0; h < 2; h++) {
                const int cv = co - 64 + h;
                const float bb = bv[cv];
                const float* v = h ? a1 : a0;
                uint32_t h0, l0, h1, l1;
                split2(v[0] + bb, v[1] + bb, h0, l0);
                split2(v[2] + bb, v[3] + bb, h1, l1);
                uint32_t off = SW((uint32_t)cv * 128 + tx * 8);
                *(uint2*)(vt + tb + off)         = make_uint2(h0, h1);
                *(uint2*)(vt + tb + 32768 + off) = make_uint2(l0, l1);
            }
        }
    }
}

// ============================================================================
// mma.sync attention, pairwise-synced warps.
// 8 warps: qg = warp>>1 (32 q rows), nh = warp&1 (32-key S slice / 128-ch V slice).
// Pair-mates (same qg) land on different SMSPs -> skew fills the tensor pipe.
// P double-buffered (buf1 reuses dead Q smem); V/K rotation guarded by a
// count-8 mbarrier that gates the prefetcher. Unnormalized exp (range-safe).
// ============================================================================
__global__ void __launch_bounds__(256, 1)
attn_kernel(const unsigned char* __restrict__ qt, const unsigned char* __restrict__ kt,
            const unsigned char* __restrict__ vt, float* __restrict__ out) {
    extern __shared__ __align__(1024) unsigned char sm[];
    const uint32_t sb = smem_u32(sm);
    const int tid  = threadIdx.x;
    const int lane = tid & 31;
    const int warp = tid >> 5;
    const int qg = warp >> 1, nh = warp & 1;
    const int b = blockIdx.y, mblk = blockIdx.x;
    const int m0 = mblk * BQ;

    const uint32_t OFF_LD0 = 0, OFF_LD1 = 8, OFF_VD0 = 16, OFF_VD1 = 24;
    const uint32_t OFF_Q = 1024;                    // 16KB; becomes PH buf1
    const uint32_t OFF_K0 = 17408, OFF_K1 = 25600;
    const uint32_t OFF_PH0 = 33792, OFF_PL0 = 50176;
    const uint32_t OFF_V0 = 66560, OFF_V1 = 132096;
    const uint32_t OFF_PL1 = 197632;

    if (tid == 0) {
        mbar_init(sb + OFF_LD0, 1);
        mbar_init(sb + OFF_LD1, 1);
        mbar_init(sb + OFF_VD0, 8);
        mbar_init(sb + OFF_VD1, 8);
    }
    // copy pre-swizzled Q tile
    {
        const uint4* s = (const uint4*)(qt + (size_t)(b * MBLKS + mblk) * QT_BYTES);
        uint4* d = (uint4*)(sm + OFF_Q);
        for (int i = tid; i < 1024; i += 256) d[i] = s[i];
    }
    __syncthreads();

    // kick off chunk 0
    if (tid == 0) {
        mbar_expect(sb + OFF_LD0, KT_BYTES + VT_BYTES);
        bulk_g2s(sb + OFF_K0, kt + (size_t)b * NCHUNK * KT_BYTES, KT_BYTES, sb + OFF_LD0);
        bulk_g2s(sb + OFF_V0, vt + (size_t)b * NCHUNK * VT_BYTES, VT_BYTES, sb + OFF_LD0);
    }

    // persistent Q fragments: [mi][ks][hb][4]
    uint32_t Qf[2][2][2][4];
    {
        const int q0b = qg * 32;
#pragma unroll
        for (int mi = 0; mi < 2; mi++)
#pragma unroll
            for (int ks = 0; ks < 2; ks++)
#pragma unroll
                for (int hb = 0; hb < 2; hb++) {
                    uint32_t row = q0b + mi * 16 + (lane & 7) + ((lane >> 3) & 1) * 8;
                    uint32_t off = hb * 64 + ks * 32 + (lane >> 4) * 16;
                    ldsm4(Qf[mi][ks][hb][0], Qf[mi][ks][hb][1], Qf[mi][ks][hb][2], Qf[mi][ks][hb][3],
                          sb + OFF_Q + SW(row * 128 + off));
                }
    }
    __syncthreads();   // Q smem is dead from here (reused as P buf1)

    float o[2][16][4];
#pragma unroll
    for (int mi = 0; mi < 2; mi++)
#pragma unroll
        for (int n = 0; n < 16; n++)
#pragma unroll
            for (int e = 0; e < 4; e++) o[mi][n][e] = 0.f;
    float lsum[2][2] = {{0.f, 0.f}, {0.f, 0.f}};

    int ph_ld[2] = {0, 0};
    const int g = lane >> 2, t = lane & 3;

    for (int ich = 0; ich < NCHUNK; ich++) {
        const int buf = ich & 1;
        const uint32_t kOff = buf ? OFF_K1 : OFF_K0;
        const uint32_t vOff = buf ? OFF_V1 : OFF_V0;
        const uint32_t pH = sb + (buf ? OFF_Q  : OFF_PH0);
        const uint32_t pL = sb + (buf ? OFF_PL1 : OFF_PL0);

        // prefetch next chunk (thread 0): wait all warps done with chunk ich-1 first
        if (tid == 0 && ich + 1 < NCHUNK) {
            if (ich >= 1) {
                int j = ich - 1;
                mbar_wait(sb + ((j & 1) ? OFF_VD1 : OFF_VD0), (j >> 1) & 1);
            }
            const uint32_t ldn = sb + (buf ? OFF_LD0 : OFF_LD1);
            mbar_expect(ldn, KT_BYTES + VT_BYTES);
            bulk_g2s(sb + (buf ? OFF_K0 : OFF_K1),
                     kt + (size_t)(b * NCHUNK + ich + 1) * KT_BYTES, KT_BYTES, ldn);
            bulk_g2s(sb + (buf ? OFF_V0 : OFF_V1),
                     vt + (size_t)(b * NCHUNK + ich + 1) * VT_BYTES, VT_BYTES, ldn);
        }
        mbar_wait(sb + (buf ? OFF_LD1 : OFF_LD0), ph_ld[buf]);
        ph_ld[buf] ^= 1;

        // ---- S = Q K^T on 32q x 32k slice; exp; write split-bf16 P ----
#pragma unroll
        for (int j = 0; j < 4; j++) {
            const uint32_t krow = nh * 32 + j * 8 + (lane & 7);
            const uint32_t koff = (lane >> 3) * 16;
            uint32_t kh[4], kl[4];
            ldsm4(kh[0], kh[1], kh[2], kh[3], sb + kOff + SW(krow * 128 + koff));
            ldsm4(kl[0], kl[1], kl[2], kl[3], sb + kOff + SW(krow * 128 + 64 + koff));

            float cs[2][4];
#pragma unroll
            for (int mi = 0; mi < 2; mi++) {
#pragma unroll
                for (int e = 0; e < 4; e++) cs[mi][e] = 0.f;
#pragma unroll
                for (int ks = 0; ks < 2; ks++) {
                    mma16816(cs[mi], Qf[mi][ks][0][0], Qf[mi][ks][0][1], Qf[mi][ks][0][2], Qf[mi][ks][0][3],
                             kh[2 * ks], kh[2 * ks + 1]);
                    mma16816(cs[mi], Qf[mi][ks][0][0], Qf[mi][ks][0][1], Qf[mi][ks][0][2], Qf[mi][ks][0][3],
                             kl[2 * ks], kl[2 * ks + 1]);
                    mma16816(cs[mi], Qf[mi][ks][1][0], Qf[mi][ks][1][1], Qf[mi][ks][1][2], Qf[mi][ks][1][3],
                             kh[2 * ks], kh[2 * ks + 1]);
                }
            }
            const uint32_t keyb = (uint32_t)(nh * 64 + j * 16 + 4 * t);
#pragma unroll
            for (int mi = 0; mi < 2; mi++) {
                const uint32_t row0 = qg * 32 + mi * 16 + g;
                float e0 = __expf(cs[mi][0]), e1 = __expf(cs[mi][1]);
                float e2 = __expf(cs[mi][2]), e3 = __expf(cs[mi][3]);
                lsum[mi][0] += e0 + e1;
                lsum[mi][1] += e2 + e3;
                uint32_t hi, lo;
                split2(e0, e1, hi, lo);
                uint32_t sw0 = SW(row0 * 128 + keyb);
                sts32(pH + sw0, hi);
                sts32(pL + sw0, lo);
                split2(e2, e3, hi, lo);
                uint32_t sw1 = SW((row0 + 8) * 128 + keyb);
                sts32(pH + sw1, hi);
                sts32(pL + sw1, lo);
            }
        }
        barsync(1 + qg);   // pairwise: both nh slices of this qg's P are ready

        // ---- O += P V  (3-term split) ----
#pragma unroll
        for (int ks = 0; ks < 4; ks++) {
            uint32_t Ph[2][4], Pl[2][4];
            const uint32_t prow = qg * 32 + (lane & 7) + ((lane >> 3) & 1) * 8;
            const uint32_t poff = ks * 32 + (lane >> 4) * 16;
#pragma unroll
            for (int mi = 0; mi < 2; mi++) {
                uint32_t sw = SW((prow + mi * 16) * 128 + poff);
                ldsm4(Ph[mi][0], Ph[mi][1], Ph[mi][2], Ph[mi][3], pH + sw);
                ldsm4(Pl[mi][0], Pl[mi][1], Pl[mi][2], Pl[mi][3], pL + sw);
            }
            const uint32_t vrow0 = nh * 128 + (lane & 7) + (lane >> 4) * 8;
            const uint32_t voff  = ks * 32 + ((lane >> 3) & 1) * 16;
#pragma unroll
            for (int jn = 0; jn < 8; jn++) {
                uint32_t vh[4], vl[4];
                uint32_t sw = SW((vrow0 + jn * 16) * 128 + voff);
                ldsm4(vh[0], vh[1], vh[2], vh[3], sb + vOff + sw);
                ldsm4(vl[0], vl[1], vl[2], vl[3], sb + vOff + 32768 + sw);
#pragma unroll
                for (int mi = 0; mi < 2; mi++) {
#pragma unroll
                    for (int nt = 0; nt < 2; nt++) {
                        float* oo = o[mi][jn * 2 + nt];
                        mma16816(oo, Ph[mi][0], Ph[mi][1], Ph[mi][2], Ph[mi][3], vh[nt * 2], vh[nt * 2 + 1]);
                        mma16816(oo, Ph[mi][0], Ph[mi][1], Ph[mi][2], Ph[mi][3], vl[nt * 2], vl[nt * 2 + 1]);
                        mma16816(oo, Pl[mi][0], Pl[mi][1], Pl[mi][2], Pl[mi][3], vh[nt * 2], vh[nt * 2 + 1]);
                    }
                }
            }
        }
        // this warp is done reading K(buf)/V(buf)
        if (lane == 0) mbar_arrive(sb + (buf ? OFF_VD1 : OFF_VD0));
    }

    // ---- epilogue: reduce row sums, normalize, transpose, store ----
    __syncthreads();
    float* Ls = (float*)(sm + OFF_PH0);     // [2][128]
#pragma unroll
    for (int mi = 0; mi < 2; mi++)
#pragma unroll
        for (int r = 0; r < 2; r++) {
            float v = lsum[mi][r];
            v += __shfl_xor_sync(0xffffffffu, v, 1);
            v += __shfl_xor_sync(0xffffffffu, v, 2);
            if (t == 0) Ls[nh * 128 + qg * 32 + mi * 16 + r * 8 + g] = v;
        }
    __syncthreads();
    float inv[2][2];
#pragma unroll
    for (int mi = 0; mi < 2; mi++)
#pragma unroll
        for (int r = 0; r < 2; r++) {
            int row = qg * 32 + mi * 16 + r * 8 + g;
            inv[mi][r] = 1.0f / (Ls[row] + Ls[128 + row]);
        }

    float* St = (float*)(sm + OFF_V0);     // [256][68]
#pragma unroll
    for (int mi = 0; mi < 2; mi++) {
        __syncthreads();
#pragma unroll
        for (int n = 0; n < 16; n++) {
            int cb = nh * 128 + n * 8 + 2 * t;
            int s0 = qg * 16 + g;
            St[cb * 68 + s0]           = o[mi][n][0] * inv[mi][0];
            St[(cb + 1) * 68 + s0]     = o[mi][n][1] * inv[mi][0];
            St[cb * 68 + s0 + 8]       = o[mi][n][2] * inv[mi][1];
            St[(cb + 1) * 68 + s0 + 8] = o[mi][n][3] * inv[mi][1];
        }
        __syncthreads();
        for (int i = tid; i < 4096; i += 256) {
            int c = i >> 4, s4 = i & 15;
            float4 v = *(float4*)&St[c * 68 + s4 * 4];
            int q = (s4 >> 2) * 32 + mi * 16 + (s4 & 3) * 4;
            *(float4*)&out[((size_t)b * C_IN + c) * NPOS + m0 + q] = v;
        }
    }
}

// ============================================================================
extern "C" void kernel_launch(void* const* d_in, const int* in_sizes, int n_in,
                              void* d_out, int out_size) {
    (void)in_sizes; (void)n_in; (void)out_size;
    const float* x  = (const float*)d_in[0];
    const float* wq = (const float*)d_in[1];
    const float* bq = (const float*)d_in[2];
    const float* wk = (const float*)d_in[3];
    const float* bk = (const float*)d_in[4];
    const float* wv = (const float*)d_in[5];
    const float* bv = (const float*)d_in[6];
    float* out = (float*)d_out;

    unsigned char *qtP, *ktP, *vtP;
    cudaGetSymbolAddress((void**)&qtP, g_qt);
    cudaGetSymbolAddress((void**)&ktP, g_kt);
    cudaGetSymbolAddress((void**)&vtP, g_vt);

    dim3 pgrid(NPOS / 64, NB);
    proj_fused_kernel<<<pgrid, 256>>>(x, wq, bq, wk, bk, wv, bv, ktP, qtP, vtP);

    const int smem = 214016;
    cudaFuncSetAttribute(attn_kernel, cudaFuncAttributeMaxDynamicSharedMemorySize, smem);
    attn_kernel<<<dim3(MBLKS, NB), 256, smem>>>(qtP, ktP, vtP, out);
}

// round 7
// speedup vs baseline: 1.3315x; 1.3315x over previous
#include <cuda_runtime.h>
#include <cuda_bf16.h>
#include <cuda_fp16.h>
#include <math.h>
#include <stdint.h>

#define C_IN 256
#define NPOS 4096
#define NB   8
#define DQK  32
#define DV   256
#define BQ   128
#define BK   64
#define NCHUNK (NPOS / BK)       // 64
#define MBLKS  (NPOS / BQ)       // 32

#define QT_BYTES 16384           // 128 rows x 128B (32c hi | 32c lo per row), bf16
#define KT_BYTES 8192            // 64 key-rows x 128B (hi | lo), bf16
#define VT_BYTES 36864           // fp16 V: 256 c-rows x 144B (64 keys, paired layout)
#define V_ROW_B  144

__device__ unsigned char g_qt[NB * MBLKS * QT_BYTES];    // Q = g (wk proj)
__device__ unsigned char g_kt[NB * NCHUNK * KT_BYTES];   // K = f (wq proj)
__device__ unsigned char g_vt[NB * NCHUNK * VT_BYTES];   // V = h (wv proj), fp16 [c][key]

// ---------------- helpers ----------------
__device__ __forceinline__ uint32_t SW(uint32_t off) {   // 128B-row swizzle (Q/K tiles)
    return off ^ ((off >> 3) & 0x70);
}
__device__ __forceinline__ uint32_t smem_u32(const void* p) {
    uint32_t a;
    asm("{ .reg .u64 t; cvta.to.shared.u64 t, %1; cvt.u32.u64 %0, t; }" : "=r"(a) : "l"(p));
    return a;
}
__device__ __forceinline__ void split2(float a, float b, uint32_t& hi, uint32_t& lo) {
    __nv_bfloat16 ha = __float2bfloat16(a), hb = __float2bfloat16(b);
    __nv_bfloat162 hh; hh.x = ha; hh.y = hb;
    hi = *reinterpret_cast<uint32_t*>(&hh);
    __nv_bfloat162 ll;
    ll.x = __float2bfloat16(a - __bfloat162float(ha));
    ll.y = __float2bfloat16(b - __bfloat162float(hb));
    lo = *reinterpret_cast<uint32_t*>(&ll);
}
__device__ __forceinline__ unsigned long long pk2(float a, float b) {
    unsigned long long r;
    asm("mov.b64 %0, {%1,%2};" : "=l"(r) : "f"(a), "f"(b));
    return r;
}
__device__ __forceinline__ float2 up2(unsigned long long v) {
    float2 r;
    asm("mov.b64 {%0,%1}, %2;" : "=f"(r.x), "=f"(r.y) : "l"(v));
    return r;
}
__device__ __forceinline__ void fma2(unsigned long long &d, unsigned long long a, unsigned long long b) {
    asm("fma.rn.f32x2 %0, %1, %2, %0;" : "+l"(d) : "l"(a), "l"(b));
}
__device__ __forceinline__ void mbar_init(uint32_t mbar, uint32_t cnt) {
    asm volatile("mbarrier.init.shared.b64 [%0], %1;" :: "r"(mbar), "r"(cnt) : "memory");
}
__device__ __forceinline__ void mbar_expect(uint32_t mbar, uint32_t bytes) {
    asm volatile("mbarrier.arrive.expect_tx.shared.b64 _, [%0], %1;" :: "r"(mbar), "r"(bytes) : "memory");
}
__device__ __forceinline__ void mbar_arrive(uint32_t mbar) {
    asm volatile("mbarrier.arrive.shared.b64 _, [%0];" :: "r"(mbar) : "memory");
}
__device__ __forceinline__ void mbar_wait(uint32_t mbar, int phase) {
    asm volatile(
        "{\n\t.reg .pred P1;\n\t"
        "LAB_WAIT_%=:\n\t"
        "mbarrier.try_wait.parity.acquire.cta.shared::cta.b64 P1, [%0], %1, 0x989680;\n\t"
        "@P1 bra LAB_DONE_%=;\n\t"
        "bra LAB_WAIT_%=;\n\t"
        "LAB_DONE_%=:\n\t}"
        :: "r"(mbar), "r"((uint32_t)phase) : "memory");
}
__device__ __forceinline__ void bulk_g2s(uint32_t dst, const void* src, uint32_t bytes, uint32_t mbar) {
    asm volatile(
        "cp.async.bulk.shared::cluster.global.mbarrier::complete_tx::bytes [%0], [%1], %2, [%3];"
        :: "r"(dst), "l"(src), "r"(bytes), "r"(mbar) : "memory");
}
__device__ __forceinline__ void sts64(uint32_t a, float v0, float v1) {
    asm volatile("st.shared.v2.f32 [%0], {%1, %2};" :: "r"(a), "f"(v0), "f"(v1));
}
__device__ __forceinline__ uint32_t lds32(uint32_t a) {
    uint32_t v;
    asm volatile("ld.shared.b32 %0, [%1];" : "=r"(v) : "r"(a));
    return v;
}
__device__ __forceinline__ void barsync(int id) {
    asm volatile("bar.sync %0, 64;" :: "r"(id) : "memory");
}
__device__ __forceinline__ void ldsm4(uint32_t& r0, uint32_t& r1, uint32_t& r2, uint32_t& r3,
                                      uint32_t addr) {
    asm volatile("ldmatrix.sync.aligned.m8n8.x4.shared.b16 {%0,%1,%2,%3}, [%4];"
                 : "=r"(r0), "=r"(r1), "=r"(r2), "=r"(r3) : "r"(addr));
}
__device__ __forceinline__ void mma16816(float* c, uint32_t a0, uint32_t a1, uint32_t a2, uint32_t a3,
                                         uint32_t b0, uint32_t b1) {
    asm volatile(
        "mma.sync.aligned.m16n8k16.row.col.f32.bf16.bf16.f32 "
        "{%0,%1,%2,%3}, {%4,%5,%6,%7}, {%8,%9}, {%0,%1,%2,%3};"
        : "+f"(c[0]), "+f"(c[1]), "+f"(c[2]), "+f"(c[3])
        : "r"(a0), "r"(a1), "r"(a2), "r"(a3), "r"(b0), "r"(b1));
}
__device__ __forceinline__ void mma_tf32(float* c, uint32_t a0, uint32_t a1, uint32_t a2, uint32_t a3,
                                         uint32_t b0, uint32_t b1) {
    asm volatile(
        "mma.sync.aligned.m16n8k8.row.col.f32.tf32.tf32.f32 "
        "{%0,%1,%2,%3}, {%4,%5,%6,%7}, {%8,%9}, {%0,%1,%2,%3};"
        : "+f"(c[0]), "+f"(c[1]), "+f"(c[2]), "+f"(c[3])
        : "r"(a0), "r"(a1), "r"(a2), "r"(a3), "r"(b0), "r"(b1));
}
__device__ __forceinline__ float tf32_rna(float x) {
    uint32_t r;
    asm("cvt.rna.tf32.f32 %0, %1;" : "=r"(r) : "f"(x));
    return __uint_as_float(r);
}

// ============================================================================
// Projections (three kernels — the R5 config that measured fastest)
// ============================================================================
template <bool ISQ>
__global__ void proj_qk_kernel(const float* __restrict__ x, const float* __restrict__ w,
                               const float* __restrict__ bias, unsigned char* __restrict__ dst) {
    __shared__ float xs[32 * 64];
    __shared__ float ws[32 * 32];
    const int tid = threadIdx.x;
    const int tx = tid & 15, ty = tid >> 4;
    const int b  = blockIdx.y;
    const int n0 = blockIdx.x * 64;

    unsigned long long acc[2][2];
#pragma unroll
    for (int j = 0; j < 2; j++) { acc[j][0] = 0ull; acc[j][1] = 0ull; }

    for (int cb = 0; cb < C_IN; cb += 32) {
        __syncthreads();
        for (int i = tid; i < 512; i += 256) {
            int cc = i >> 4, nq = i & 15;
            ((float4*)xs)[cc * 16 + nq] =
                *(const float4*)&x[((size_t)b * C_IN + cb + cc) * NPOS + n0 + nq * 4];
        }
        {
            int co = tid >> 3, c4 = tid & 7;
            ((float4*)ws)[tid] = *(const float4*)&w[co * C_IN + cb + c4 * 4];
        }
        __syncthreads();
#pragma unroll 4
        for (int cc = 0; cc < 32; cc++) {
            ulonglong2 xv = *(ulonglong2*)&xs[cc * 64 + tx * 4];
#pragma unroll
            for (int j = 0; j < 2; j++) {
                float wv_ = ws[(ty * 2 + j) * 32 + cc];
                unsigned long long wp = pk2(wv_, wv_);
                fma2(acc[j][0], xv.x, wp);
                fma2(acc[j][1], xv.y, wp);
            }
        }
    }
    const int co0 = ty * 2;
    const float bv0 = bias[co0], bv1 = bias[co0 + 1];
    float a0[4], a1[4];
    { float2 t = up2(acc[0][0]); a0[0] = t.x + bv0; a0[1] = t.y + bv0;
      t = up2(acc[0][1]); a0[2] = t.x + bv0; a0[3] = t.y + bv0; }
    { float2 t = up2(acc[1][0]); a1[0] = t.x + bv1; a1[1] = t.y + bv1;
      t = up2(acc[1][1]); a1[2] = t.x + bv1; a1[3] = t.y + bv1; }
#pragma unroll
    for (int r = 0; r < 4; r++) {
        int n = n0 + tx * 4 + r;
        uint32_t hi, lo;
        split2(a0[r], a1[r], hi, lo);
        size_t tb; uint32_t row;
        if (ISQ) { tb = ((size_t)b * MBLKS  + (n >> 7)) * QT_BYTES; row = n & 127; }
        else     { tb = ((size_t)b * NCHUNK + (n >> 6)) * KT_BYTES; row = n & 63;  }
        *(uint32_t*)(dst + tb + SW(row * 128 + co0 * 2))       = hi;
        *(uint32_t*)(dst + tb + SW(row * 128 + 64 + co0 * 2))  = lo;
    }
}

// V projection -> fp16 tile [c][key], row stride 144B, keys stored as pairs
// (k, k+4) packed per 32-bit word for conflict-free tf32 B-fragment loads.
__global__ void proj_v_kernel(const float* __restrict__ x, const float* __restrict__ w,
                              const float* __restrict__ bias, unsigned char* __restrict__ dst) {
    __shared__ float xs[32 * 64];
    __shared__ float ws[256 * 32];
    const int tid = threadIdx.x;
    const int tx = tid & 15, ty = tid >> 4;
    const int b  = blockIdx.y;
    const int n0 = blockIdx.x * 64;

    unsigned long long acc[16][2];
#pragma unroll
    for (int j = 0; j < 16; j++) { acc[j][0] = 0ull; acc[j][1] = 0ull; }

    for (int cb = 0; cb < C_IN; cb += 32) {
        __syncthreads();
        for (int i = tid; i < 512; i += 256) {
            int cc = i >> 4, nq = i & 15;
            ((float4*)xs)[cc * 16 + nq] =
                *(const float4*)&x[((size_t)b * C_IN + cb + cc) * NPOS + n0 + nq * 4];
        }
        for (int i = tid; i < 2048; i += 256) {
            int co = i >> 3, c4 = i & 7;
            ((float4*)ws)[i] = *(const float4*)&w[co * C_IN + cb + c4 * 4];
        }
        __syncthreads();
#pragma unroll 4
        for (int cc = 0; cc < 32; cc++) {
            ulonglong2 xv = *(ulonglong2*)&xs[cc * 64 + tx * 4];
#pragma unroll
            for (int j = 0; j < 16; j++) {
                float wv_ = ws[(ty * 16 + j) * 32 + cc];
                unsigned long long wp = pk2(wv_, wv_);
                fma2(acc[j][0], xv.x, wp);
                fma2(acc[j][1], xv.y, wp);
            }
        }
    }
    const size_t tb = ((size_t)b * NCHUNK + (n0 >> 6)) * VT_BYTES;
#pragma unroll
    for (int j = 0; j < 16; j++) {
        int co = ty * 16 + j;
        float bb = bias[co];
        float v[4];
        { float2 t = up2(acc[j][0]); v[0] = t.x + bb; v[1] = t.y + bb;
          t = up2(acc[j][1]); v[2] = t.x + bb; v[3] = t.y + bb; }
#pragma unroll
        for (int r = 0; r < 4; r++) {
            int k = tx * 4 + r;   // key within chunk (0..63)
            uint32_t koff = ((k >> 3) << 4) + ((k & 3) << 2) + (((k >> 2) & 1) << 1);
            *(__half*)(dst + tb + (uint32_t)co * V_ROW_B + koff) = __float2half(v[r]);
        }
    }
}

// ============================================================================
// Attention: S = bf16 3-term mma (unchanged), exp -> P fp32(tf32-rounded) smem,
// PV = single-term tf32 m16n8k8 with fp16 V. Unnormalized softmax, O in regs.
// 8 warps: qg = warp>>1 (32 q rows), nh = warp&1 (32-key S slice / 128-ch V slice).
// ============================================================================
__global__ void __launch_bounds__(256, 1)
attn_kernel(const unsigned char* __restrict__ qt, const unsigned char* __restrict__ kt,
            const unsigned char* __restrict__ vt, float* __restrict__ out) {
    extern __shared__ __align__(1024) unsigned char sm[];
    const uint32_t sb = smem_u32(sm);
    const int tid  = threadIdx.x;
    const int lane = tid & 31;
    const int warp = tid >> 5;
    const int qg = warp >> 1, nh = warp & 1;
    const int b = blockIdx.y, mblk = blockIdx.x;
    const int m0 = mblk * BQ;

    const uint32_t OFF_LD0 = 0, OFF_LD1 = 8, OFF_VD0 = 16, OFF_VD1 = 24;
    const uint32_t OFF_Q  = 1024;
    const uint32_t OFF_K0 = 17408, OFF_K1 = 25600;
    const uint32_t OFF_P0 = 33792, OFF_P1 = 68608;     // fp32 P: 128 x 68 words
    const uint32_t OFF_V0 = 103424, OFF_V1 = 140288;   // fp16 V: 256 x 144B

    if (tid == 0) {
        mbar_init(sb + OFF_LD0, 1);
        mbar_init(sb + OFF_LD1, 1);
        mbar_init(sb + OFF_VD0, 8);
        mbar_init(sb + OFF_VD1, 8);
    }
    {
        const uint4* s = (const uint4*)(qt + (size_t)(b * MBLKS + mblk) * QT_BYTES);
        uint4* d = (uint4*)(sm + OFF_Q);
        for (int i = tid; i < 1024; i += 256) d[i] = s[i];
    }
    __syncthreads();

    if (tid == 0) {
        mbar_expect(sb + OFF_LD0, KT_BYTES + VT_BYTES);
        bulk_g2s(sb + OFF_K0, kt + (size_t)b * NCHUNK * KT_BYTES, KT_BYTES, sb + OFF_LD0);
        bulk_g2s(sb + OFF_V0, vt + (size_t)b * NCHUNK * VT_BYTES, VT_BYTES, sb + OFF_LD0);
    }

    // persistent Q fragments
    uint32_t Qf[2][2][2][4];
    {
        const int q0b = qg * 32;
#pragma unroll
        for (int mi = 0; mi < 2; mi++)
#pragma unroll
            for (int ks = 0; ks < 2; ks++)
#pragma unroll
                for (int hb = 0; hb < 2; hb++) {
                    uint32_t row = q0b + mi * 16 + (lane & 7) + ((lane >> 3) & 1) * 8;
                    uint32_t off = hb * 64 + ks * 32 + (lane >> 4) * 16;
                    ldsm4(Qf[mi][ks][hb][0], Qf[mi][ks][hb][1], Qf[mi][ks][hb][2], Qf[mi][ks][hb][3],
                          sb + OFF_Q + SW(row * 128 + off));
                }
    }

    float o[2][16][4];
#pragma unroll
    for (int mi = 0; mi < 2; mi++)
#pragma unroll
        for (int n = 0; n < 16; n++)
#pragma unroll
            for (int e = 0; e < 4; e++) o[mi][n][e] = 0.f;
    float lsum[2][2] = {{0.f, 0.f}, {0.f, 0.f}};

    int ph_ld[2] = {0, 0};
    const int g = lane >> 2, t = lane & 3;

    for (int ich = 0; ich < NCHUNK; ich++) {
        const int buf = ich & 1;
        const uint32_t kOff = buf ? OFF_K1 : OFF_K0;
        const uint32_t vOff = buf ? OFF_V1 : OFF_V0;
        const uint32_t pP = sb + (buf ? OFF_P1 : OFF_P0);

        if (tid == 0 && ich + 1 < NCHUNK) {
            if (ich >= 1) {
                int j = ich - 1;
                mbar_wait(sb + ((j & 1) ? OFF_VD1 : OFF_VD0), (j >> 1) & 1);
            }
            const uint32_t ldn = sb + (buf ? OFF_LD0 : OFF_LD1);
            mbar_expect(ldn, KT_BYTES + VT_BYTES);
            bulk_g2s(sb + (buf ? OFF_K0 : OFF_K1),
                     kt + (size_t)(b * NCHUNK + ich + 1) * KT_BYTES, KT_BYTES, ldn);
            bulk_g2s(sb + (buf ? OFF_V0 : OFF_V1),
                     vt + (size_t)(b * NCHUNK + ich + 1) * VT_BYTES, VT_BYTES, ldn);
        }
        mbar_wait(sb + (buf ? OFF_LD1 : OFF_LD0), ph_ld[buf]);
        ph_ld[buf] ^= 1;

        // ---- S = Q K^T (bf16, 3-term); exp; store tf32-rounded fp32 P ----
#pragma unroll
        for (int j = 0; j < 4; j++) {
            const uint32_t krow = nh * 32 + j * 8 + (lane & 7);
            const uint32_t koff = (lane >> 3) * 16;
            uint32_t kh[4], kl[4];
            ldsm4(kh[0], kh[1], kh[2], kh[3], sb + kOff + SW(krow * 128 + koff));
            ldsm4(kl[0], kl[1], kl[2], kl[3], sb + kOff + SW(krow * 128 + 64 + koff));

            float cs[2][4];
#pragma unroll
            for (int mi = 0; mi < 2; mi++) {
#pragma unroll
                for (int e = 0; e < 4; e++) cs[mi][e] = 0.f;
#pragma unroll
                for (int ks = 0; ks < 2; ks++) {
                    mma16816(cs[mi], Qf[mi][ks][0][0], Qf[mi][ks][0][1], Qf[mi][ks][0][2], Qf[mi][ks][0][3],
                             kh[2 * ks], kh[2 * ks + 1]);
                    mma16816(cs[mi], Qf[mi][ks][0][0], Qf[mi][ks][0][1], Qf[mi][ks][0][2], Qf[mi][ks][0][3],
                             kl[2 * ks], kl[2 * ks + 1]);
                    mma16816(cs[mi], Qf[mi][ks][1][0], Qf[mi][ks][1][1], Qf[mi][ks][1][2], Qf[mi][ks][1][3],
                             kh[2 * ks], kh[2 * ks + 1]);
                }
            }
            const uint32_t key0 = (uint32_t)(nh * 32 + j * 8 + 2 * t);
#pragma unroll
            for (int mi = 0; mi < 2; mi++) {
                const uint32_t row0 = qg * 32 + mi * 16 + g;
                float e0 = tf32_rna(__expf(cs[mi][0]));
                float e1 = tf32_rna(__expf(cs[mi][1]));
                float e2 = tf32_rna(__expf(cs[mi][2]));
                float e3 = tf32_rna(__expf(cs[mi][3]));
                lsum[mi][0] += e0 + e1;
                lsum[mi][1] += e2 + e3;
                sts64(pP + (row0 * 68 + key0) * 4, e0, e1);
                sts64(pP + ((row0 + 8) * 68 + key0) * 4, e2, e3);
            }
        }
        barsync(1 + qg);   // both nh slices of this qg's P are ready

        // ---- O += P V  (tf32 single-term, fp16 V) ----
#pragma unroll
        for (int ks = 0; ks < 8; ks++) {
            uint32_t A[2][4];
#pragma unroll
            for (int mi = 0; mi < 2; mi++) {
                uint32_t r = qg * 32 + mi * 16 + g;
                uint32_t base = pP + (r * 68 + ks * 8 + t) * 4;
                A[mi][0] = lds32(base);
                A[mi][1] = lds32(base + 8 * 68 * 4);
                A[mi][2] = lds32(base + 4 * 4);
                A[mi][3] = lds32(base + (8 * 68 + 4) * 4);
            }
#pragma unroll
            for (int jn = 0; jn < 16; jn++) {
                uint32_t c = nh * 128 + jn * 8 + g;
                uint32_t vp = lds32(sb + vOff + c * V_ROW_B + ks * 16 + t * 4);
                __half2 vh = *reinterpret_cast<__half2*>(&vp);
                float2 vf = __half22float2(vh);
                uint32_t b0 = __float_as_uint(vf.x);
                uint32_t b1 = __float_as_uint(vf.y);
                mma_tf32(o[0][jn], A[0][0], A[0][1], A[0][2], A[0][3], b0, b1);
                mma_tf32(o[1][jn], A[1][0], A[1][1], A[1][2], A[1][3], b0, b1);
            }
        }
        if (lane == 0) mbar_arrive(sb + (buf ? OFF_VD1 : OFF_VD0));
    }

    // ---- epilogue: reduce row sums, normalize, transpose, store ----
    __syncthreads();
    float* Ls = (float*)(sm + OFF_P0);     // [2][128]
#pragma unroll
    for (int mi = 0; mi < 2; mi++)
#pragma unroll
        for (int r = 0; r < 2; r++) {
            float v = lsum[mi][r];
            v += __shfl_xor_sync(0xffffffffu, v, 1);
            v += __shfl_xor_sync(0xffffffffu, v, 2);
            if (t == 0) Ls[nh * 128 + qg * 32 + mi * 16 + r * 8 + g] = v;
        }
    __syncthreads();
    float inv[2][2];
#pragma unroll
    for (int mi = 0; mi < 2; mi++)
#pragma unroll
        for (int r = 0; r < 2; r++) {
            int row = qg * 32 + mi * 16 + r * 8 + g;
            inv[mi][r] = 1.0f / (Ls[row] + Ls[128 + row]);
        }

    float* St = (float*)(sm + OFF_V0);     // [256][68] floats (69632B fits V0+V1)
#pragma unroll
    for (int mi = 0; mi < 2; mi++) {
        __syncthreads();
#pragma unroll
        for (int n = 0; n < 16; n++) {
            int cb = nh * 128 + n * 8 + 2 * t;
            int s0 = qg * 16 + g;
            St[cb * 68 + s0]           = o[mi][n][0] * inv[mi][0];
            St[(cb + 1) * 68 + s0]     = o[mi][n][1] * inv[mi][0];
            St[cb * 68 + s0 + 8]       = o[mi][n][2] * inv[mi][1];
            St[(cb + 1) * 68 + s0 + 8] = o[mi][n][3] * inv[mi][1];
        }
        __syncthreads();
        for (int i = tid; i < 4096; i += 256) {
            int c = i >> 4, s4 = i & 15;
            float4 v = *(float4*)&St[c * 68 + s4 * 4];
            int q = (s4 >> 2) * 32 + mi * 16 + (s4 & 3) * 4;
            *(float4*)&out[((size_t)b * C_IN + c) * NPOS + m0 + q] = v;
        }
    }
}

// ============================================================================
extern "C" void kernel_launch(void* const* d_in, const int* in_sizes, int n_in,
                              void* d_out, int out_size) {
    (void)in_sizes; (void)n_in; (void)out_size;
    const float* x  = (const float*)d_in[0];
    const float* wq = (const float*)d_in[1];
    const float* bq = (const float*)d_in[2];
    const float* wk = (const float*)d_in[3];
    const float* bk = (const float*)d_in[4];
    const float* wv = (const float*)d_in[5];
    const float* bv = (const float*)d_in[6];
    float* out = (float*)d_out;

    unsigned char *qtP, *ktP, *vtP;
    cudaGetSymbolAddress((void**)&qtP, g_qt);
    cudaGetSymbolAddress((void**)&ktP, g_kt);
    cudaGetSymbolAddress((void**)&vtP, g_vt);

    dim3 pgrid(NPOS / 64, NB);
    proj_qk_kernel<false><<<pgrid, 256>>>(x, wq, bq, ktP);   // f = keys
    proj_qk_kernel<true ><<<pgrid, 256>>>(x, wk, bk, qtP);   // g = queries
    proj_v_kernel<<<pgrid, 256>>>(x, wv, bv, vtP);           // h = values

    const int smem = 177152;
    cudaFuncSetAttribute(attn_kernel, cudaFuncAttributeMaxDynamicSharedMemorySize, smem);
    attn_kernel<<<dim3(MBLKS, NB), 256, smem>>>(qtP, ktP, vtP, out);
}

// round 8
// speedup vs baseline: 1.3392x; 1.0058x over previous
#include <cuda_runtime.h>
#include <cuda_bf16.h>
#include <cuda_fp16.h>
#include <math.h>
#include <stdint.h>

#define C_IN 256
#define NPOS 4096
#define NB   8
#define DQK  32
#define DV   256
#define BQ   128
#define BK   64
#define NCHUNK (NPOS / BK)       // 64
#define MBLKS  (NPOS / BQ)       // 32

#define QT_BYTES 16384           // 128 rows x 128B (32c hi | 32c lo per row), bf16
#define KT_BYTES 8192            // 64 key-rows x 128B (hi | lo), bf16
#define VT_BYTES 36864           // fp16 V: 256 c-rows x 144B (64 keys, paired layout)
#define V_ROW_B  144

__device__ unsigned char g_qt[NB * MBLKS * QT_BYTES];    // Q = g (wk proj)
__device__ unsigned char g_kt[NB * NCHUNK * KT_BYTES];   // K = f (wq proj)
__device__ unsigned char g_vt[NB * NCHUNK * VT_BYTES];   // V = h (wv proj), fp16 [c][key]

// ---------------- helpers ----------------
__device__ __forceinline__ uint32_t SW(uint32_t off) {
    return off ^ ((off >> 3) & 0x70);
}
__device__ __forceinline__ uint32_t smem_u32(const void* p) {
    uint32_t a;
    asm("{ .reg .u64 t; cvta.to.shared.u64 t, %1; cvt.u32.u64 %0, t; }" : "=r"(a) : "l"(p));
    return a;
}
__device__ __forceinline__ void split2(float a, float b, uint32_t& hi, uint32_t& lo) {
    __nv_bfloat16 ha = __float2bfloat16(a), hb = __float2bfloat16(b);
    __nv_bfloat162 hh; hh.x = ha; hh.y = hb;
    hi = *reinterpret_cast<uint32_t*>(&hh);
    __nv_bfloat162 ll;
    ll.x = __float2bfloat16(a - __bfloat162float(ha));
    ll.y = __float2bfloat16(b - __bfloat162float(hb));
    lo = *reinterpret_cast<uint32_t*>(&ll);
}
__device__ __forceinline__ unsigned long long pk2(float a, float b) {
    unsigned long long r;
    asm("mov.b64 %0, {%1,%2};" : "=l"(r) : "f"(a), "f"(b));
    return r;
}
__device__ __forceinline__ float2 up2(unsigned long long v) {
    float2 r;
    asm("mov.b64 {%0,%1}, %2;" : "=f"(r.x), "=f"(r.y) : "l"(v));
    return r;
}
__device__ __forceinline__ void fma2(unsigned long long &d, unsigned long long a, unsigned long long b) {
    asm("fma.rn.f32x2 %0, %1, %2, %0;" : "+l"(d) : "l"(a), "l"(b));
}
__device__ __forceinline__ void mbar_init(uint32_t mbar, uint32_t cnt) {
    asm volatile("mbarrier.init.shared.b64 [%0], %1;" :: "r"(mbar), "r"(cnt) : "memory");
}
__device__ __forceinline__ void mbar_expect(uint32_t mbar, uint32_t bytes) {
    asm volatile("mbarrier.arrive.expect_tx.shared.b64 _, [%0], %1;" :: "r"(mbar), "r"(bytes) : "memory");
}
__device__ __forceinline__ void mbar_arrive(uint32_t mbar) {
    asm volatile("mbarrier.arrive.shared.b64 _, [%0];" :: "r"(mbar) : "memory");
}
__device__ __forceinline__ void mbar_wait(uint32_t mbar, int phase) {
    asm volatile(
        "{\n\t.reg .pred P1;\n\t"
        "LAB_WAIT_%=:\n\t"
        "mbarrier.try_wait.parity.acquire.cta.shared::cta.b64 P1, [%0], %1, 0x989680;\n\t"
        "@P1 bra LAB_DONE_%=;\n\t"
        "bra LAB_WAIT_%=;\n\t"
        "LAB_DONE_%=:\n\t}"
        :: "r"(mbar), "r"((uint32_t)phase) : "memory");
}
__device__ __forceinline__ void bulk_g2s(uint32_t dst, const void* src, uint32_t bytes, uint32_t mbar) {
    asm volatile(
        "cp.async.bulk.shared::cluster.global.mbarrier::complete_tx::bytes [%0], [%1], %2, [%3];"
        :: "r"(dst), "l"(src), "r"(bytes), "r"(mbar) : "memory");
}
__device__ __forceinline__ void sts64(uint32_t a, float v0, float v1) {
    asm volatile("st.shared.v2.f32 [%0], {%1, %2};" :: "r"(a), "f"(v0), "f"(v1));
}
__device__ __forceinline__ uint32_t lds32(uint32_t a) {
    uint32_t v;
    asm volatile("ld.shared.b32 %0, [%1];" : "=r"(v) : "r"(a));
    return v;
}
__device__ __forceinline__ void barsync(int id) {
    asm volatile("bar.sync %0, 64;" :: "r"(id) : "memory");
}
__device__ __forceinline__ void ldsm4(uint32_t& r0, uint32_t& r1, uint32_t& r2, uint32_t& r3,
                                      uint32_t addr) {
    asm volatile("ldmatrix.sync.aligned.m8n8.x4.shared.b16 {%0,%1,%2,%3}, [%4];"
                 : "=r"(r0), "=r"(r1), "=r"(r2), "=r"(r3) : "r"(addr));
}
__device__ __forceinline__ void mma16816(float* c, uint32_t a0, uint32_t a1, uint32_t a2, uint32_t a3,
                                         uint32_t b0, uint32_t b1) {
    asm volatile(
        "mma.sync.aligned.m16n8k16.row.col.f32.bf16.bf16.f32 "
        "{%0,%1,%2,%3}, {%4,%5,%6,%7}, {%8,%9}, {%0,%1,%2,%3};"
        : "+f"(c[0]), "+f"(c[1]), "+f"(c[2]), "+f"(c[3])
        : "r"(a0), "r"(a1), "r"(a2), "r"(a3), "r"(b0), "r"(b1));
}
__device__ __forceinline__ void mma_tf32(float* c, uint32_t a0, uint32_t a1, uint32_t a2, uint32_t a3,
                                         uint32_t b0, uint32_t b1) {
    asm volatile(
        "mma.sync.aligned.m16n8k8.row.col.f32.tf32.tf32.f32 "
        "{%0,%1,%2,%3}, {%4,%5,%6,%7}, {%8,%9}, {%0,%1,%2,%3};"
        : "+f"(c[0]), "+f"(c[1]), "+f"(c[2]), "+f"(c[3])
        : "r"(a0), "r"(a1), "r"(a2), "r"(a3), "r"(b0), "r"(b1));
}
__device__ __forceinline__ float tf32_rna(float x) {
    uint32_t r;
    asm("cvt.rna.tf32.f32 %0, %1;" : "=r"(r) : "f"(x));
    return __uint_as_float(r);
}

// ============================================================================
// Projections (unchanged from R7)
// ============================================================================
template <bool ISQ>
__global__ void proj_qk_kernel(const float* __restrict__ x, const float* __restrict__ w,
                               const float* __restrict__ bias, unsigned char* __restrict__ dst) {
    __shared__ float xs[32 * 64];
    __shared__ float ws[32 * 32];
    const int tid = threadIdx.x;
    const int tx = tid & 15, ty = tid >> 4;
    const int b  = blockIdx.y;
    const int n0 = blockIdx.x * 64;

    unsigned long long acc[2][2];
#pragma unroll
    for (int j = 0; j < 2; j++) { acc[j][0] = 0ull; acc[j][1] = 0ull; }

    for (int cb = 0; cb < C_IN; cb += 32) {
        __syncthreads();
        for (int i = tid; i < 512; i += 256) {
            int cc = i >> 4, nq = i & 15;
            ((float4*)xs)[cc * 16 + nq] =
                *(const float4*)&x[((size_t)b * C_IN + cb + cc) * NPOS + n0 + nq * 4];
        }
        {
            int co = tid >> 3, c4 = tid & 7;
            ((float4*)ws)[tid] = *(const float4*)&w[co * C_IN + cb + c4 * 4];
        }
        __syncthreads();
#pragma unroll 4
        for (int cc = 0; cc < 32; cc++) {
            ulonglong2 xv = *(ulonglong2*)&xs[cc * 64 + tx * 4];
#pragma unroll
            for (int j = 0; j < 2; j++) {
                float wv_ = ws[(ty * 2 + j) * 32 + cc];
                unsigned long long wp = pk2(wv_, wv_);
                fma2(acc[j][0], xv.x, wp);
                fma2(acc[j][1], xv.y, wp);
            }
        }
    }
    const int co0 = ty * 2;
    const float bv0 = bias[co0], bv1 = bias[co0 + 1];
    float a0[4], a1[4];
    { float2 t = up2(acc[0][0]); a0[0] = t.x + bv0; a0[1] = t.y + bv0;
      t = up2(acc[0][1]); a0[2] = t.x + bv0; a0[3] = t.y + bv0; }
    { float2 t = up2(acc[1][0]); a1[0] = t.x + bv1; a1[1] = t.y + bv1;
      t = up2(acc[1][1]); a1[2] = t.x + bv1; a1[3] = t.y + bv1; }
#pragma unroll
    for (int r = 0; r < 4; r++) {
        int n = n0 + tx * 4 + r;
        uint32_t hi, lo;
        split2(a0[r], a1[r], hi, lo);
        size_t tb; uint32_t row;
        if (ISQ) { tb = ((size_t)b * MBLKS  + (n >> 7)) * QT_BYTES; row = n & 127; }
        else     { tb = ((size_t)b * NCHUNK + (n >> 6)) * KT_BYTES; row = n & 63;  }
        *(uint32_t*)(dst + tb + SW(row * 128 + co0 * 2))       = hi;
        *(uint32_t*)(dst + tb + SW(row * 128 + 64 + co0 * 2))  = lo;
    }
}

__global__ void proj_v_kernel(const float* __restrict__ x, const float* __restrict__ w,
                              const float* __restrict__ bias, unsigned char* __restrict__ dst) {
    __shared__ float xs[32 * 64];
    __shared__ float ws[256 * 32];
    const int tid = threadIdx.x;
    const int tx = tid & 15, ty = tid >> 4;
    const int b  = blockIdx.y;
    const int n0 = blockIdx.x * 64;

    unsigned long long acc[16][2];
#pragma unroll
    for (int j = 0; j < 16; j++) { acc[j][0] = 0ull; acc[j][1] = 0ull; }

    for (int cb = 0; cb < C_IN; cb += 32) {
        __syncthreads();
        for (int i = tid; i < 512; i += 256) {
            int cc = i >> 4, nq = i & 15;
            ((float4*)xs)[cc * 16 + nq] =
                *(const float4*)&x[((size_t)b * C_IN + cb + cc) * NPOS + n0 + nq * 4];
        }
        for (int i = tid; i < 2048; i += 256) {
            int co = i >> 3, c4 = i & 7;
            ((float4*)ws)[i] = *(const float4*)&w[co * C_IN + cb + c4 * 4];
        }
        __syncthreads();
#pragma unroll 4
        for (int cc = 0; cc < 32; cc++) {
            ulonglong2 xv = *(ulonglong2*)&xs[cc * 64 + tx * 4];
#pragma unroll
            for (int j = 0; j < 16; j++) {
                float wv_ = ws[(ty * 16 + j) * 32 + cc];
                unsigned long long wp = pk2(wv_, wv_);
                fma2(acc[j][0], xv.x, wp);
                fma2(acc[j][1], xv.y, wp);
            }
        }
    }
    const size_t tb = ((size_t)b * NCHUNK + (n0 >> 6)) * VT_BYTES;
#pragma unroll
    for (int j = 0; j < 16; j++) {
        int co = ty * 16 + j;
        float bb = bias[co];
        float v[4];
        { float2 t = up2(acc[j][0]); v[0] = t.x + bb; v[1] = t.y + bb;
          t = up2(acc[j][1]); v[2] = t.x + bb; v[3] = t.y + bb; }
#pragma unroll
        for (int r = 0; r < 4; r++) {
            int k = tx * 4 + r;
            uint32_t koff = ((k >> 3) << 4) + ((k & 3) << 2) + (((k >> 2) & 1) << 1);
            *(__half*)(dst + tb + (uint32_t)co * V_ROW_B + koff) = __float2half(v[r]);
        }
    }
}

// ============================================================================
// Attention, software-pipelined: body(i) = PV(i) interleaved with S(i+1)+exp.
// K/V triple-buffered, P double-buffered. 8 warps: qg=warp>>1, nh=warp&1.
// ============================================================================
__global__ void __launch_bounds__(256, 1)
attn_kernel(const unsigned char* __restrict__ qt, const unsigned char* __restrict__ kt,
            const unsigned char* __restrict__ vt, float* __restrict__ out) {
    extern __shared__ __align__(1024) unsigned char sm[];
    const uint32_t sb = smem_u32(sm);
    const int tid  = threadIdx.x;
    const int lane = tid & 31;
    const int warp = tid >> 5;
    const int qg = warp >> 1, nh = warp & 1;
    const int b = blockIdx.y, mblk = blockIdx.x;
    const int m0 = mblk * BQ;

    const uint32_t OFF_LD[3] = {0, 8, 16};
    const uint32_t OFF_VD[3] = {24, 32, 40};
    const uint32_t OFF_Q = 1024;
    const uint32_t OFF_K[3] = {17408, 25600, 33792};
    const uint32_t OFF_P[2] = {41984, 76800};          // fp32 P: 128 x 68 words
    const uint32_t OFF_V[3] = {111616, 148480, 185344};// fp16 V: 256 x 144B

    if (tid == 0) {
#pragma unroll
        for (int s = 0; s < 3; s++) {
            mbar_init(sb + OFF_LD[s], 1);
            mbar_init(sb + OFF_VD[s], 8);
        }
    }
    {
        const uint4* s = (const uint4*)(qt + (size_t)(b * MBLKS + mblk) * QT_BYTES);
        uint4* d = (uint4*)(sm + OFF_Q);
        for (int i = tid; i < 1024; i += 256) d[i] = s[i];
    }
    __syncthreads();

    if (tid == 0) {
#pragma unroll
        for (int j = 0; j < 2; j++) {
            mbar_expect(sb + OFF_LD[j], KT_BYTES + VT_BYTES);
            bulk_g2s(sb + OFF_K[j], kt + (size_t)(b * NCHUNK + j) * KT_BYTES, KT_BYTES, sb + OFF_LD[j]);
            bulk_g2s(sb + OFF_V[j], vt + (size_t)(b * NCHUNK + j) * VT_BYTES, VT_BYTES, sb + OFF_LD[j]);
        }
    }

    // persistent Q fragments
    uint32_t Qf[2][2][2][4];
    {
        const int q0b = qg * 32;
#pragma unroll
        for (int mi = 0; mi < 2; mi++)
#pragma unroll
            for (int ks = 0; ks < 2; ks++)
#pragma unroll
                for (int hb = 0; hb < 2; hb++) {
                    uint32_t row = q0b + mi * 16 + (lane & 7) + ((lane >> 3) & 1) * 8;
                    uint32_t off = hb * 64 + ks * 32 + (lane >> 4) * 16;
                    ldsm4(Qf[mi][ks][hb][0], Qf[mi][ks][hb][1], Qf[mi][ks][hb][2], Qf[mi][ks][hb][3],
                          sb + OFF_Q + SW(row * 128 + off));
                }
    }

    float o[2][16][4];
#pragma unroll
    for (int mi = 0; mi < 2; mi++)
#pragma unroll
        for (int n = 0; n < 16; n++)
#pragma unroll
            for (int e = 0; e < 4; e++) o[mi][n][e] = 0.f;
    float lsum[2][2] = {{0.f, 0.f}, {0.f, 0.f}};

    const int g = lane >> 2, t = lane & 3;

    // ---- S j-block: score 8 keys of chunk (K at kOff), exp, store P at pDst
#define S_BLOCK(j, kOff, pDst)                                                              \
    {                                                                                       \
        const uint32_t krow = nh * 32 + (j) * 8 + (lane & 7);                               \
        const uint32_t koff = (lane >> 3) * 16;                                             \
        uint32_t kh[4], kl[4];                                                              \
        ldsm4(kh[0], kh[1], kh[2], kh[3], (kOff) + SW(krow * 128 + koff));                  \
        ldsm4(kl[0], kl[1], kl[2], kl[3], (kOff) + SW(krow * 128 + 64 + koff));             \
        float cs[2][4];                                                                     \
        _Pragma("unroll")                                                                   \
        for (int mi = 0; mi < 2; mi++) {                                                    \
            _Pragma("unroll")                                                               \
            for (int e = 0; e < 4; e++) cs[mi][e] = 0.f;                                    \
            _Pragma("unroll")                                                               \
            for (int ks = 0; ks < 2; ks++) {                                                \
                mma16816(cs[mi], Qf[mi][ks][0][0], Qf[mi][ks][0][1], Qf[mi][ks][0][2],      \
                         Qf[mi][ks][0][3], kh[2 * ks], kh[2 * ks + 1]);                     \
                mma16816(cs[mi], Qf[mi][ks][0][0], Qf[mi][ks][0][1], Qf[mi][ks][0][2],      \
                         Qf[mi][ks][0][3], kl[2 * ks], kl[2 * ks + 1]);                     \
                mma16816(cs[mi], Qf[mi][ks][1][0], Qf[mi][ks][1][1], Qf[mi][ks][1][2],      \
                         Qf[mi][ks][1][3], kh[2 * ks], kh[2 * ks + 1]);                     \
            }                                                                               \
        }                                                                                   \
        const uint32_t key0 = (uint32_t)(nh * 32 + (j) * 8 + 2 * t);                        \
        _Pragma("unroll")                                                                   \
        for (int mi = 0; mi < 2; mi++) {                                                    \
            const uint32_t row0 = qg * 32 + mi * 16 + g;                                    \
            float e0 = tf32_rna(__expf(cs[mi][0]));                                         \
            float e1 = tf32_rna(__expf(cs[mi][1]));                                         \
            float e2 = tf32_rna(__expf(cs[mi][2]));                                         \
            float e3 = tf32_rna(__expf(cs[mi][3]));                                         \
            lsum[mi][0] += e0 + e1;                                                         \
            lsum[mi][1] += e2 + e3;                                                         \
            sts64((pDst) + (row0 * 68 + key0) * 4, e0, e1);                                 \
            sts64((pDst) + ((row0 + 8) * 68 + key0) * 4, e2, e3);                           \
        }                                                                                   \
    }

    // ---- PV ks-block: one k8 slice (8 keys) of PV(i)
#define PV_BLOCK(ks, pSrc, vOff)                                                            \
    {                                                                                       \
        uint32_t A[2][4];                                                                   \
        _Pragma("unroll")                                                                   \
        for (int mi = 0; mi < 2; mi++) {                                                    \
            uint32_t r = qg * 32 + mi * 16 + g;                                             \
            uint32_t base = (pSrc) + (r * 68 + (ks) * 8 + t) * 4;                           \
            A[mi][0] = lds32(base);                                                         \
            A[mi][1] = lds32(base + 8 * 68 * 4);                                            \
            A[mi][2] = lds32(base + 4 * 4);                                                 \
            A[mi][3] = lds32(base + (8 * 68 + 4) * 4);                                      \
        }                                                                                   \
        _Pragma("unroll")                                                                   \
        for (int jn = 0; jn < 16; jn++) {                                                   \
            uint32_t c = nh * 128 + jn * 8 + g;                                             \
            uint32_t vp = lds32((vOff) + c * V_ROW_B + (ks) * 16 + t * 4);                  \
            __half2 vh2 = *reinterpret_cast<__half2*>(&vp);                                 \
            float2 vf = __half22float2(vh2);                                                \
            uint32_t b0 = __float_as_uint(vf.x);                                            \
            uint32_t b1 = __float_as_uint(vf.y);                                            \
            mma_tf32(o[0][jn], A[0][0], A[0][1], A[0][2], A[0][3], b0, b1);                 \
            mma_tf32(o[1][jn], A[1][0], A[1][1], A[1][2], A[1][3], b0, b1);                 \
        }                                                                                   \
    }

    // ---- prologue: S(0) -> P0
    mbar_wait(sb + OFF_LD[0], 0);
    {
        const uint32_t k0 = sb + OFF_K[0], p0 = sb + OFF_P[0];
#pragma unroll
        for (int j = 0; j < 4; j++) S_BLOCK(j, k0, p0)
    }
    barsync(1 + qg);

    // ---- pipelined mainloop: PV(i) + S(i+1)
    for (int ich = 0; ich < NCHUNK - 1; ich++) {
        const uint32_t vOff = sb + OFF_V[ich % 3];
        const uint32_t kOffN = sb + OFF_K[(ich + 1) % 3];
        const uint32_t pCur = sb + OFF_P[ich & 1];
        const uint32_t pNxt = sb + OFF_P[(ich + 1) & 1];

        if (tid == 0) {
            if (ich >= 1) mbar_wait(sb + OFF_VD[(ich - 1) % 3], ((ich - 1) / 3) & 1);
            if (ich + 2 < NCHUNK) {
                const int jn = ich + 2;
                const uint32_t ldn = sb + OFF_LD[jn % 3];
                mbar_expect(ldn, KT_BYTES + VT_BYTES);
                bulk_g2s(sb + OFF_K[jn % 3], kt + (size_t)(b * NCHUNK + jn) * KT_BYTES, KT_BYTES, ldn);
                bulk_g2s(sb + OFF_V[jn % 3], vt + (size_t)(b * NCHUNK + jn) * VT_BYTES, VT_BYTES, ldn);
            }
        }

        PV_BLOCK(0, pCur, vOff)
        PV_BLOCK(1, pCur, vOff)
        mbar_wait(sb + OFF_LD[(ich + 1) % 3], ((ich + 1) / 3) & 1);
        S_BLOCK(0, kOffN, pNxt)
        PV_BLOCK(2, pCur, vOff)
        PV_BLOCK(3, pCur, vOff)
        S_BLOCK(1, kOffN, pNxt)
        PV_BLOCK(4, pCur, vOff)
        PV_BLOCK(5, pCur, vOff)
        S_BLOCK(2, kOffN, pNxt)
        PV_BLOCK(6, pCur, vOff)
        PV_BLOCK(7, pCur, vOff)
        S_BLOCK(3, kOffN, pNxt)

        if (lane == 0) mbar_arrive(sb + OFF_VD[ich % 3]);
        barsync(1 + qg);
    }

    // ---- final chunk PV(63)
    {
        const uint32_t vOff = sb + OFF_V[(NCHUNK - 1) % 3];
        const uint32_t pCur = sb + OFF_P[(NCHUNK - 1) & 1];
#pragma unroll
        for (int ks = 0; ks < 8; ks++) PV_BLOCK(ks, pCur, vOff)
    }

    // ---- epilogue: reduce row sums, normalize, transpose, store
    __syncthreads();
    float* Ls = (float*)(sm + OFF_P[0]);     // [2][128]
#pragma unroll
    for (int mi = 0; mi < 2; mi++)
#pragma unroll
        for (int r = 0; r < 2; r++) {
            float v = lsum[mi][r];
            v += __shfl_xor_sync(0xffffffffu, v, 1);
            v += __shfl_xor_sync(0xffffffffu, v, 2);
            if (t == 0) Ls[nh * 128 + qg * 32 + mi * 16 + r * 8 + g] = v;
        }
    __syncthreads();
    float inv[2][2];
#pragma unroll
    for (int mi = 0; mi < 2; mi++)
#pragma unroll
        for (int r = 0; r < 2; r++) {
            int row = qg * 32 + mi * 16 + r * 8 + g;
            inv[mi][r] = 1.0f / (Ls[row] + Ls[128 + row]);
        }

    float* St = (float*)(sm + OFF_V[0]);     // [256][68] floats
#pragma unroll
    for (int mi = 0; mi < 2; mi++) {
        __syncthreads();
#pragma unroll
        for (int n = 0; n < 16; n++) {
            int cb = nh * 128 + n * 8 + 2 * t;
            int s0 = qg * 16 + g;
            St[cb * 68 + s0]           = o[mi][n][0] * inv[mi][0];
            St[(cb + 1) * 68 + s0]     = o[mi][n][1] * inv[mi][0];
            St[cb * 68 + s0 + 8]       = o[mi][n][2] * inv[mi][1];
            St[(cb + 1) * 68 + s0 + 8] = o[mi][n][3] * inv[mi][1];
        }
        __syncthreads();
        for (int i = tid; i < 4096; i += 256) {
            int c = i >> 4, s4 = i & 15;
            float4 v = *(float4*)&St[c * 68 + s4 * 4];
            int q = (s4 >> 2) * 32 + mi * 16 + (s4 & 3) * 4;
            *(float4*)&out[((size_t)b * C_IN + c) * NPOS + m0 + q] = v;
        }
    }
#undef S_BLOCK
#undef PV_BLOCK
}

// ============================================================================
extern "C" void kernel_launch(void* const* d_in, const int* in_sizes, int n_in,
                              void* d_out, int out_size) {
    (void)in_sizes; (void)n_in; (void)out_size;
    const float* x  = (const float*)d_in[0];
    const float* wq = (const float*)d_in[1];
    const float* bq = (const float*)d_in[2];
    const float* wk = (const float*)d_in[3];
    const float* bk = (const float*)d_in[4];
    const float* wv = (const float*)d_in[5];
    const float* bv = (const float*)d_in[6];
    float* out = (float*)d_out;

    unsigned char *qtP, *ktP, *vtP;
    cudaGetSymbolAddress((void**)&qtP, g_qt);
    cudaGetSymbolAddress((void**)&ktP, g_kt);
    cudaGetSymbolAddress((void**)&vtP, g_vt);

    dim3 pgrid(NPOS / 64, NB);
    proj_qk_kernel<false><<<pgrid, 256>>>(x, wq, bq, ktP);   // f = keys
    proj_qk_kernel<true ><<<pgrid, 256>>>(x, wk, bk, qtP);   // g = queries
    proj_v_kernel<<<pgrid, 256>>>(x, wv, bv, vtP);           // h = values

    const int smem = 222208;
    cudaFuncSetAttribute(attn_kernel, cudaFuncAttributeMaxDynamicSharedMemorySize, smem);
    attn_kernel<<<dim3(MBLKS, NB), 256, smem>>>(qtP, ktP, vtP, out);
}

// round 9
// speedup vs baseline: 1.7147x; 1.2803x over previous
#include <cuda_runtime.h>
#include <cuda_bf16.h>
#include <cuda_fp16.h>
#include <math.h>
#include <stdint.h>

#define C_IN 256
#define NPOS 4096
#define NB   8
#define DQK  32
#define DV   256
#define BQ   128
#define BK   64
#define NCHUNK (NPOS / BK)       // 64
#define MBLKS  (NPOS / BQ)       // 32
#define SHIFT  14.0f             // fixed softmax shift: exp(s-14) fits fp16

#define QT_BYTES 16384           // 128 rows x 128B (32c hi | 32c lo per row), bf16
#define KT_BYTES 8192            // 64 key-rows x 128B (hi | lo), bf16
#define VT_BYTES 32768           // fp16 V: 256 c-rows x 128B (64 keys), swizzled

__device__ unsigned char g_qt[NB * MBLKS * QT_BYTES];    // Q = g (wk proj)
__device__ unsigned char g_kt[NB * NCHUNK * KT_BYTES];   // K = f (wq proj)
__device__ unsigned char g_vt[NB * NCHUNK * VT_BYTES];   // V = h (wv proj), fp16 [c][key]

// ---------------- helpers ----------------
__device__ __forceinline__ uint32_t SW(uint32_t off) {
    return off ^ ((off >> 3) & 0x70);
}
__device__ __forceinline__ uint32_t smem_u32(const void* p) {
    uint32_t a;
    asm("{ .reg .u64 t; cvta.to.shared.u64 t, %1; cvt.u32.u64 %0, t; }" : "=r"(a) : "l"(p));
    return a;
}
__device__ __forceinline__ void split2(float a, float b, uint32_t& hi, uint32_t& lo) {
    __nv_bfloat16 ha = __float2bfloat16(a), hb = __float2bfloat16(b);
    __nv_bfloat162 hh; hh.x = ha; hh.y = hb;
    hi = *reinterpret_cast<uint32_t*>(&hh);
    __nv_bfloat162 ll;
    ll.x = __float2bfloat16(a - __bfloat162float(ha));
    ll.y = __float2bfloat16(b - __bfloat162float(hb));
    lo = *reinterpret_cast<uint32_t*>(&ll);
}
__device__ __forceinline__ unsigned long long pk2(float a, float b) {
    unsigned long long r;
    asm("mov.b64 %0, {%1,%2};" : "=l"(r) : "f"(a), "f"(b));
    return r;
}
__device__ __forceinline__ float2 up2(unsigned long long v) {
    float2 r;
    asm("mov.b64 {%0,%1}, %2;" : "=f"(r.x), "=f"(r.y) : "l"(v));
    return r;
}
__device__ __forceinline__ void fma2(unsigned long long &d, unsigned long long a, unsigned long long b) {
    asm("fma.rn.f32x2 %0, %1, %2, %0;" : "+l"(d) : "l"(a), "l"(b));
}
__device__ __forceinline__ void mbar_init(uint32_t mbar, uint32_t cnt) {
    asm volatile("mbarrier.init.shared.b64 [%0], %1;" :: "r"(mbar), "r"(cnt) : "memory");
}
__device__ __forceinline__ void mbar_expect(uint32_t mbar, uint32_t bytes) {
    asm volatile("mbarrier.arrive.expect_tx.shared.b64 _, [%0], %1;" :: "r"(mbar), "r"(bytes) : "memory");
}
__device__ __forceinline__ void mbar_arrive(uint32_t mbar) {
    asm volatile("mbarrier.arrive.shared.b64 _, [%0];" :: "r"(mbar) : "memory");
}
__device__ __forceinline__ void mbar_wait(uint32_t mbar, int phase) {
    asm volatile(
        "{\n\t.reg .pred P1;\n\t"
        "LAB_WAIT_%=:\n\t"
        "mbarrier.try_wait.parity.acquire.cta.shared::cta.b64 P1, [%0], %1, 0x989680;\n\t"
        "@P1 bra LAB_DONE_%=;\n\t"
        "bra LAB_WAIT_%=;\n\t"
        "LAB_DONE_%=:\n\t}"
        :: "r"(mbar), "r"((uint32_t)phase) : "memory");
}
__device__ __forceinline__ void bulk_g2s(uint32_t dst, const void* src, uint32_t bytes, uint32_t mbar) {
    asm volatile(
        "cp.async.bulk.shared::cluster.global.mbarrier::complete_tx::bytes [%0], [%1], %2, [%3];"
        :: "r"(dst), "l"(src), "r"(bytes), "r"(mbar) : "memory");
}
__device__ __forceinline__ void sts32(uint32_t a, uint32_t v) {
    asm volatile("st.shared.b32 [%0], %1;" :: "r"(a), "r"(v));
}
__device__ __forceinline__ void barsync(int id) {
    asm volatile("bar.sync %0, 64;" :: "r"(id) : "memory");
}
__device__ __forceinline__ void ldsm4(uint32_t& r0, uint32_t& r1, uint32_t& r2, uint32_t& r3,
                                      uint32_t addr) {
    asm volatile("ldmatrix.sync.aligned.m8n8.x4.shared.b16 {%0,%1,%2,%3}, [%4];"
                 : "=r"(r0), "=r"(r1), "=r"(r2), "=r"(r3) : "r"(addr));
}
__device__ __forceinline__ void mma16816(float* c, uint32_t a0, uint32_t a1, uint32_t a2, uint32_t a3,
                                         uint32_t b0, uint32_t b1) {
    asm volatile(
        "mma.sync.aligned.m16n8k16.row.col.f32.bf16.bf16.f32 "
        "{%0,%1,%2,%3}, {%4,%5,%6,%7}, {%8,%9}, {%0,%1,%2,%3};"
        : "+f"(c[0]), "+f"(c[1]), "+f"(c[2]), "+f"(c[3])
        : "r"(a0), "r"(a1), "r"(a2), "r"(a3), "r"(b0), "r"(b1));
}
__device__ __forceinline__ void mma_f16(float* c, uint32_t a0, uint32_t a1, uint32_t a2, uint32_t a3,
                                        uint32_t b0, uint32_t b1) {
    asm volatile(
        "mma.sync.aligned.m16n8k16.row.col.f32.f16.f16.f32 "
        "{%0,%1,%2,%3}, {%4,%5,%6,%7}, {%8,%9}, {%0,%1,%2,%3};"
        : "+f"(c[0]), "+f"(c[1]), "+f"(c[2]), "+f"(c[3])
        : "r"(a0), "r"(a1), "r"(a2), "r"(a3), "r"(b0), "r"(b1));
}

// ============================================================================
// Projections
// ============================================================================
template <bool ISQ>
__global__ void proj_qk_kernel(const float* __restrict__ x, const float* __restrict__ w,
                               const float* __restrict__ bias, unsigned char* __restrict__ dst) {
    __shared__ float xs[32 * 64];
    __shared__ float ws[32 * 32];
    const int tid = threadIdx.x;
    const int tx = tid & 15, ty = tid >> 4;
    const int b  = blockIdx.y;
    const int n0 = blockIdx.x * 64;

    unsigned long long acc[2][2];
#pragma unroll
    for (int j = 0; j < 2; j++) { acc[j][0] = 0ull; acc[j][1] = 0ull; }

    for (int cb = 0; cb < C_IN; cb += 32) {
        __syncthreads();
        for (int i = tid; i < 512; i += 256) {
            int cc = i >> 4, nq = i & 15;
            ((float4*)xs)[cc * 16 + nq] =
                *(const float4*)&x[((size_t)b * C_IN + cb + cc) * NPOS + n0 + nq * 4];
        }
        {
            int co = tid >> 3, c4 = tid & 7;
            ((float4*)ws)[tid] = *(const float4*)&w[co * C_IN + cb + c4 * 4];
        }
        __syncthreads();
#pragma unroll 4
        for (int cc = 0; cc < 32; cc++) {
            ulonglong2 xv = *(ulonglong2*)&xs[cc * 64 + tx * 4];
#pragma unroll
            for (int j = 0; j < 2; j++) {
                float wv_ = ws[(ty * 2 + j) * 32 + cc];
                unsigned long long wp = pk2(wv_, wv_);
                fma2(acc[j][0], xv.x, wp);
                fma2(acc[j][1], xv.y, wp);
            }
        }
    }
    const int co0 = ty * 2;
    const float bv0 = bias[co0], bv1 = bias[co0 + 1];
    float a0[4], a1[4];
    { float2 t = up2(acc[0][0]); a0[0] = t.x + bv0; a0[1] = t.y + bv0;
      t = up2(acc[0][1]); a0[2] = t.x + bv0; a0[3] = t.y + bv0; }
    { float2 t = up2(acc[1][0]); a1[0] = t.x + bv1; a1[1] = t.y + bv1;
      t = up2(acc[1][1]); a1[2] = t.x + bv1; a1[3] = t.y + bv1; }
#pragma unroll
    for (int r = 0; r < 4; r++) {
        int n = n0 + tx * 4 + r;
        uint32_t hi, lo;
        split2(a0[r], a1[r], hi, lo);
        size_t tb; uint32_t row;
        if (ISQ) { tb = ((size_t)b * MBLKS  + (n >> 7)) * QT_BYTES; row = n & 127; }
        else     { tb = ((size_t)b * NCHUNK + (n >> 6)) * KT_BYTES; row = n & 63;  }
        *(uint32_t*)(dst + tb + SW(row * 128 + co0 * 2))       = hi;
        *(uint32_t*)(dst + tb + SW(row * 128 + 64 + co0 * 2))  = lo;
    }
}

// V projection -> fp16 tile [c][key], 128B swizzled rows (ldmatrix-ready)
__global__ void proj_v_kernel(const float* __restrict__ x, const float* __restrict__ w,
                              const float* __restrict__ bias, unsigned char* __restrict__ dst) {
    __shared__ float xs[32 * 64];
    __shared__ float ws[256 * 32];
    const int tid = threadIdx.x;
    const int tx = tid & 15, ty = tid >> 4;
    const int b  = blockIdx.y;
    const int n0 = blockIdx.x * 64;

    unsigned long long acc[16][2];
#pragma unroll
    for (int j = 0; j < 16; j++) { acc[j][0] = 0ull; acc[j][1] = 0ull; }

    for (int cb = 0; cb < C_IN; cb += 32) {
        __syncthreads();
        for (int i = tid; i < 512; i += 256) {
            int cc = i >> 4, nq = i & 15;
            ((float4*)xs)[cc * 16 + nq] =
                *(const float4*)&x[((size_t)b * C_IN + cb + cc) * NPOS + n0 + nq * 4];
        }
        for (int i = tid; i < 2048; i += 256) {
            int co = i >> 3, c4 = i & 7;
            ((float4*)ws)[i] = *(const float4*)&w[co * C_IN + cb + c4 * 4];
        }
        __syncthreads();
#pragma unroll 4
        for (int cc = 0; cc < 32; cc++) {
            ulonglong2 xv = *(ulonglong2*)&xs[cc * 64 + tx * 4];
#pragma unroll
            for (int j = 0; j < 16; j++) {
                float wv_ = ws[(ty * 16 + j) * 32 + cc];
                unsigned long long wp = pk2(wv_, wv_);
                fma2(acc[j][0], xv.x, wp);
                fma2(acc[j][1], xv.y, wp);
            }
        }
    }
    const size_t tb = ((size_t)b * NCHUNK + (n0 >> 6)) * VT_BYTES;
#pragma unroll
    for (int j = 0; j < 16; j++) {
        int co = ty * 16 + j;
        float bb = bias[co];
        float v[4];
        { float2 t = up2(acc[j][0]); v[0] = t.x + bb; v[1] = t.y + bb;
          t = up2(acc[j][1]); v[2] = t.x + bb; v[3] = t.y + bb; }
        __half2 p0 = __floats2half2_rn(v[0], v[1]);
        __half2 p1 = __floats2half2_rn(v[2], v[3]);
        // keys tx*4 .. tx*4+3 -> bytes tx*8 (8B-aligned; SW preserves 8B blocks)
        uint32_t off = SW((uint32_t)co * 128 + tx * 8);
        *(uint2*)(dst + tb + off) = make_uint2(*(uint32_t*)&p0, *(uint32_t*)&p1);
    }
}

// ============================================================================
// Attention: S bf16 3-term, exp(s-SHIFT) -> fp16 P (128B swizzled rows),
// PV = fp16 m16n8k16, all operands via ldmatrix. Pipelined PV(i) + S(i+1).
// 8 warps: qg=warp>>1 (32 q rows), nh=warp&1 (32-key S slice / 128-ch V slice).
// ============================================================================
__global__ void __launch_bounds__(256, 1)
attn_kernel(const unsigned char* __restrict__ qt, const unsigned char* __restrict__ kt,
            const unsigned char* __restrict__ vt, float* __restrict__ out) {
    extern __shared__ __align__(1024) unsigned char sm[];
    const uint32_t sb = smem_u32(sm);
    const int tid  = threadIdx.x;
    const int lane = tid & 31;
    const int warp = tid >> 5;
    const int qg = warp >> 1, nh = warp & 1;
    const int b = blockIdx.y, mblk = blockIdx.x;
    const int m0 = mblk * BQ;

    const uint32_t OFF_LD[3] = {0, 8, 16};
    const uint32_t OFF_VD[3] = {24, 32, 40};
    const uint32_t OFF_Q = 1024;
    const uint32_t OFF_K[3] = {17408, 25600, 33792};
    const uint32_t OFF_P[2] = {41984, 58368};          // fp16 P: 128 x 128B
    const uint32_t OFF_V[3] = {74752, 107520, 140288}; // fp16 V: 256 x 128B

    if (tid == 0) {
#pragma unroll
        for (int s = 0; s < 3; s++) {
            mbar_init(sb + OFF_LD[s], 1);
            mbar_init(sb + OFF_VD[s], 8);
        }
    }
    {
        const uint4* s = (const uint4*)(qt + (size_t)(b * MBLKS + mblk) * QT_BYTES);
        uint4* d = (uint4*)(sm + OFF_Q);
        for (int i = tid; i < 1024; i += 256) d[i] = s[i];
    }
    __syncthreads();

    if (tid == 0) {
#pragma unroll
        for (int j = 0; j < 2; j++) {
            mbar_expect(sb + OFF_LD[j], KT_BYTES + VT_BYTES);
            bulk_g2s(sb + OFF_K[j], kt + (size_t)(b * NCHUNK + j) * KT_BYTES, KT_BYTES, sb + OFF_LD[j]);
            bulk_g2s(sb + OFF_V[j], vt + (size_t)(b * NCHUNK + j) * VT_BYTES, VT_BYTES, sb + OFF_LD[j]);
        }
    }

    // persistent Q fragments
    uint32_t Qf[2][2][2][4];
    {
        const int q0b = qg * 32;
#pragma unroll
        for (int mi = 0; mi < 2; mi++)
#pragma unroll
            for (int ks = 0; ks < 2; ks++)
#pragma unroll
                for (int hb = 0; hb < 2; hb++) {
                    uint32_t row = q0b + mi * 16 + (lane & 7) + ((lane >> 3) & 1) * 8;
                    uint32_t off = hb * 64 + ks * 32 + (lane >> 4) * 16;
                    ldsm4(Qf[mi][ks][hb][0], Qf[mi][ks][hb][1], Qf[mi][ks][hb][2], Qf[mi][ks][hb][3],
                          sb + OFF_Q + SW(row * 128 + off));
                }
    }

    float o[2][16][4];
#pragma unroll
    for (int mi = 0; mi < 2; mi++)
#pragma unroll
        for (int n = 0; n < 16; n++)
#pragma unroll
            for (int e = 0; e < 4; e++) o[mi][n][e] = 0.f;
    float lsum[2][2] = {{0.f, 0.f}, {0.f, 0.f}};

    const int g = lane >> 2, t = lane & 3;

    // S j-block: 8 keys of next chunk -> exp(s-SHIFT) -> fp16 P
#define S_BLOCK(j, kOff, pDst)                                                              \
    {                                                                                       \
        const uint32_t krow = nh * 32 + (j) * 8 + (lane & 7);                               \
        const uint32_t koff = (lane >> 3) * 16;                                             \
        uint32_t kh[4], kl[4];                                                              \
        ldsm4(kh[0], kh[1], kh[2], kh[3], (kOff) + SW(krow * 128 + koff));                  \
        ldsm4(kl[0], kl[1], kl[2], kl[3], (kOff) + SW(krow * 128 + 64 + koff));             \
        float cs[2][4];                                                                     \
        _Pragma("unroll")                                                                   \
        for (int mi = 0; mi < 2; mi++) {                                                    \
            _Pragma("unroll")                                                               \
            for (int e = 0; e < 4; e++) cs[mi][e] = 0.f;                                    \
            _Pragma("unroll")                                                               \
            for (int ks = 0; ks < 2; ks++) {                                                \
                mma16816(cs[mi], Qf[mi][ks][0][0], Qf[mi][ks][0][1], Qf[mi][ks][0][2],      \
                         Qf[mi][ks][0][3], kh[2 * ks], kh[2 * ks + 1]);                     \
                mma16816(cs[mi], Qf[mi][ks][0][0], Qf[mi][ks][0][1], Qf[mi][ks][0][2],      \
                         Qf[mi][ks][0][3], kl[2 * ks], kl[2 * ks + 1]);                     \
                mma16816(cs[mi], Qf[mi][ks][1][0], Qf[mi][ks][1][1], Qf[mi][ks][1][2],      \
                         Qf[mi][ks][1][3], kh[2 * ks], kh[2 * ks + 1]);                     \
            }                                                                               \
        }                                                                                   \
        const uint32_t keyb = (uint32_t)(nh * 64 + (j) * 16 + 4 * t);                       \
        _Pragma("unroll")                                                                   \
        for (int mi = 0; mi < 2; mi++) {                                                    \
            const uint32_t row0 = qg * 32 + mi * 16 + g;                                    \
            float e0 = __expf(cs[mi][0] - SHIFT), e1 = __expf(cs[mi][1] - SHIFT);           \
            float e2 = __expf(cs[mi][2] - SHIFT), e3 = __expf(cs[mi][3] - SHIFT);           \
            lsum[mi][0] += e0 + e1;                                                         \
            lsum[mi][1] += e2 + e3;                                                         \
            __half2 h01 = __floats2half2_rn(e0, e1);                                        \
            __half2 h23 = __floats2half2_rn(e2, e3);                                        \
            sts32((pDst) + SW(row0 * 128 + keyb), *(uint32_t*)&h01);                        \
            sts32((pDst) + SW((row0 + 8) * 128 + keyb), *(uint32_t*)&h23);                  \
        }                                                                                   \
    }

    // PV ks16-block: 16 keys, fp16 m16n8k16, all ldmatrix
#define PV_BLOCK(ks16, pSrc, vOff)                                                          \
    {                                                                                       \
        uint32_t A[2][4];                                                                   \
        _Pragma("unroll")                                                                   \
        for (int mi = 0; mi < 2; mi++) {                                                    \
            uint32_t row = qg * 32 + mi * 16 + (lane & 7) + ((lane >> 3) & 1) * 8;          \
            ldsm4(A[mi][0], A[mi][1], A[mi][2], A[mi][3],                                   \
                  (pSrc) + SW(row * 128 + (ks16) * 32 + (lane >> 4) * 16));                 \
        }                                                                                   \
        _Pragma("unroll")                                                                   \
        for (int jnp = 0; jnp < 8; jnp++) {                                                 \
            uint32_t vrow = nh * 128 + jnp * 16 + (lane & 7) + ((lane >> 4) & 1) * 8;       \
            uint32_t vcol = (ks16) * 32 + ((lane >> 3) & 1) * 16;                           \
            uint32_t B0, B1, B2, B3;                                                        \
            ldsm4(B0, B1, B2, B3, (vOff) + SW(vrow * 128 + vcol));                          \
            _Pragma("unroll")                                                               \
            for (int mi = 0; mi < 2; mi++) {                                                \
                mma_f16(o[mi][jnp * 2],     A[mi][0], A[mi][1], A[mi][2], A[mi][3], B0, B1);\
                mma_f16(o[mi][jnp * 2 + 1], A[mi][0], A[mi][1], A[mi][2], A[mi][3], B2, B3);\
            }                                                                               \
        }                                                                                   \
    }

    // ---- prologue: S(0) -> P0
    mbar_wait(sb + OFF_LD[0], 0);
    {
        const uint32_t k0 = sb + OFF_K[0], p0 = sb + OFF_P[0];
#pragma unroll
        for (int j = 0; j < 4; j++) S_BLOCK(j, k0, p0)
    }
    barsync(1 + qg);

    // ---- pipelined mainloop: PV(i) interleaved with S(i+1)
    for (int ich = 0; ich < NCHUNK - 1; ich++) {
        const uint32_t vOff = sb + OFF_V[ich % 3];
        const uint32_t kOffN = sb + OFF_K[(ich + 1) % 3];
        const uint32_t pCur = sb + OFF_P[ich & 1];
        const uint32_t pNxt = sb + OFF_P[(ich + 1) & 1];

        if (tid == 0) {
            if (ich >= 1) mbar_wait(sb + OFF_VD[(ich - 1) % 3], ((ich - 1) / 3) & 1);
            if (ich + 2 < NCHUNK) {
                const int jn = ich + 2;
                const uint32_t ldn = sb + OFF_LD[jn % 3];
                mbar_expect(ldn, KT_BYTES + VT_BYTES);
                bulk_g2s(sb + OFF_K[jn % 3], kt + (size_t)(b * NCHUNK + jn) * KT_BYTES, KT_BYTES, ldn);
                bulk_g2s(sb + OFF_V[jn % 3], vt + (size_t)(b * NCHUNK + jn) * VT_BYTES, VT_BYTES, ldn);
            }
        }

        PV_BLOCK(0, pCur, vOff)
        mbar_wait(sb + OFF_LD[(ich + 1) % 3], ((ich + 1) / 3) & 1);
        S_BLOCK(0, kOffN, pNxt)
        PV_BLOCK(1, pCur, vOff)
        S_BLOCK(1, kOffN, pNxt)
        PV_BLOCK(2, pCur, vOff)
        S_BLOCK(2, kOffN, pNxt)
        PV_BLOCK(3, pCur, vOff)
        S_BLOCK(3, kOffN, pNxt)

        if (lane == 0) mbar_arrive(sb + OFF_VD[ich % 3]);
        barsync(1 + qg);
    }

    // ---- final chunk PV
    {
        const uint32_t vOff = sb + OFF_V[(NCHUNK - 1) % 3];
        const uint32_t pCur = sb + OFF_P[(NCHUNK - 1) & 1];
#pragma unroll
        for (int ks = 0; ks < 4; ks++) PV_BLOCK(ks, pCur, vOff)
    }

    // ---- epilogue: reduce row sums, normalize, transpose, store
    __syncthreads();
    float* Ls = (float*)(sm + OFF_P[0]);     // [2][128]
#pragma unroll
    for (int mi = 0; mi < 2; mi++)
#pragma unroll
        for (int r = 0; r < 2; r++) {
            float v = lsum[mi][r];
            v += __shfl_xor_sync(0xffffffffu, v, 1);
            v += __shfl_xor_sync(0xffffffffu, v, 2);
            if (t == 0) Ls[nh * 128 + qg * 32 + mi * 16 + r * 8 + g] = v;
        }
    __syncthreads();
    float inv[2][2];
#pragma unroll
    for (int mi = 0; mi < 2; mi++)
#pragma unroll
        for (int r = 0; r < 2; r++) {
            int row = qg * 32 + mi * 16 + r * 8 + g;
            inv[mi][r] = 1.0f / (Ls[row] + Ls[128 + row]);
        }

    float* St = (float*)(sm + OFF_V[0]);     // [256][68] floats
#pragma unroll
    for (int mi = 0; mi < 2; mi++) {
        __syncthreads();
#pragma unroll
        for (int n = 0; n < 16; n++) {
            int cb = nh * 128 + n * 8 + 2 * t;
            int s0 = qg * 16 + g;
            St[cb * 68 + s0]           = o[mi][n][0] * inv[mi][0];
            St[(cb + 1) * 68 + s0]     = o[mi][n][1] * inv[mi][0];
            St[cb * 68 + s0 + 8]       = o[mi][n][2] * inv[mi][1];
            St[(cb + 1) * 68 + s0 + 8] = o[mi][n][3] * inv[mi][1];
        }
        __syncthreads();
        for (int i = tid; i < 4096; i += 256) {
            int c = i >> 4, s4 = i & 15;
            float4 v = *(float4*)&St[c * 68 + s4 * 4];
            int q = (s4 >> 2) * 32 + mi * 16 + (s4 & 3) * 4;
            *(float4*)&out[((size_t)b * C_IN + c) * NPOS + m0 + q] = v;
        }
    }
#undef S_BLOCK
#undef PV_BLOCK
}

// ============================================================================
extern "C" void kernel_launch(void* const* d_in, const int* in_sizes, int n_in,
                              void* d_out, int out_size) {
    (void)in_sizes; (void)n_in; (void)out_size;
    const float* x  = (const float*)d_in[0];
    const float* wq = (const float*)d_in[1];
    const float* bq = (const float*)d_in[2];
    const float* wk = (const float*)d_in[3];
    const float* bk = (const float*)d_in[4];
    const float* wv = (const float*)d_in[5];
    const float* bv = (const float*)d_in[6];
    float* out = (float*)d_out;

    unsigned char *qtP, *ktP, *vtP;
    cudaGetSymbolAddress((void**)&qtP, g_qt);
    cudaGetSymbolAddress((void**)&ktP, g_kt);
    cudaGetSymbolAddress((void**)&vtP, g_vt);

    dim3 pgrid(NPOS / 64, NB);
    proj_qk_kernel<false><<<pgrid, 256>>>(x, wq, bq, ktP);   // f = keys
    proj_qk_kernel<true ><<<pgrid, 256>>>(x, wk, bk, qtP);   // g = queries
    proj_v_kernel<<<pgrid, 256>>>(x, wv, bv, vtP);           // h = values

    const int smem = 173056;
    cudaFuncSetAttribute(attn_kernel, cudaFuncAttributeMaxDynamicSharedMemorySize, smem);
    attn_kernel<<<dim3(MBLKS, NB), 256, smem>>>(qtP, ktP, vtP, out);
}

// round 10
// speedup vs baseline: 2.1680x; 1.2644x over previous
#include <cuda_runtime.h>
#include <cuda_bf16.h>
#include <cuda_fp16.h>
#include <math.h>
#include <stdint.h>

#define C_IN 256
#define NPOS 4096
#define NB   8
#define DQK  32
#define DV   256
#define BQ   128
#define BK   64
#define NCHUNK (NPOS / BK)       // 64
#define MBLKS  (NPOS / BQ)       // 32
#define SHIFT  14.0f             // fixed softmax shift: exp(s-14) fits fp16

#define QT_BYTES 16384           // 128 rows x 128B (32c hi | 32c lo per row), bf16
#define KT_BYTES 8192            // 64 key-rows x 128B (hi | lo), bf16
#define VT_BYTES 32768           // fp16 V: 256 c-rows x 128B (64 keys), swizzled
#define WT_CHUNK 40960           // one K-chunk of split weights: 320 ch x 128B

__device__ unsigned char g_qt[NB * MBLKS * QT_BYTES];    // Q = g (wk proj)
__device__ unsigned char g_kt[NB * NCHUNK * KT_BYTES];   // K = f (wq proj)
__device__ unsigned char g_vt[NB * NCHUNK * VT_BYTES];   // V = h (wv proj), fp16 [c][key]
__device__ unsigned char g_wt[8 * WT_CHUNK];             // split weights, 8 K-chunks

// ---------------- helpers ----------------
__device__ __forceinline__ uint32_t SW(uint32_t off) {
    return off ^ ((off >> 3) & 0x70);
}
__device__ __forceinline__ uint32_t smem_u32(const void* p) {
    uint32_t a;
    asm("{ .reg .u64 t; cvta.to.shared.u64 t, %1; cvt.u32.u64 %0, t; }" : "=r"(a) : "l"(p));
    return a;
}
__device__ __forceinline__ void split2(float a, float b, uint32_t& hi, uint32_t& lo) {
    __nv_bfloat16 ha = __float2bfloat16(a), hb = __float2bfloat16(b);
    __nv_bfloat162 hh; hh.x = ha; hh.y = hb;
    hi = *reinterpret_cast<uint32_t*>(&hh);
    __nv_bfloat162 ll;
    ll.x = __float2bfloat16(a - __bfloat162float(ha));
    ll.y = __float2bfloat16(b - __bfloat162float(hb));
    lo = *reinterpret_cast<uint32_t*>(&ll);
}
__device__ __forceinline__ void mbar_init(uint32_t mbar, uint32_t cnt) {
    asm volatile("mbarrier.init.shared.b64 [%0], %1;" :: "r"(mbar), "r"(cnt) : "memory");
}
__device__ __forceinline__ void mbar_expect(uint32_t mbar, uint32_t bytes) {
    asm volatile("mbarrier.arrive.expect_tx.shared.b64 _, [%0], %1;" :: "r"(mbar), "r"(bytes) : "memory");
}
__device__ __forceinline__ void mbar_arrive(uint32_t mbar) {
    asm volatile("mbarrier.arrive.shared.b64 _, [%0];" :: "r"(mbar) : "memory");
}
__device__ __forceinline__ void mbar_wait(uint32_t mbar, int phase) {
    asm volatile(
        "{\n\t.reg .pred P1;\n\t"
        "LAB_WAIT_%=:\n\t"
        "mbarrier.try_wait.parity.acquire.cta.shared::cta.b64 P1, [%0], %1, 0x989680;\n\t"
        "@P1 bra LAB_DONE_%=;\n\t"
        "bra LAB_WAIT_%=;\n\t"
        "LAB_DONE_%=:\n\t}"
        :: "r"(mbar), "r"((uint32_t)phase) : "memory");
}
__device__ __forceinline__ void bulk_g2s(uint32_t dst, const void* src, uint32_t bytes, uint32_t mbar) {
    asm volatile(
        "cp.async.bulk.shared::cluster.global.mbarrier::complete_tx::bytes [%0], [%1], %2, [%3];"
        :: "r"(dst), "l"(src), "r"(bytes), "r"(mbar) : "memory");
}
__device__ __forceinline__ void sts32(uint32_t a, uint32_t v) {
    asm volatile("st.shared.b32 [%0], %1;" :: "r"(a), "r"(v));
}
__device__ __forceinline__ void barsync(int id) {
    asm volatile("bar.sync %0, 64;" :: "r"(id) : "memory");
}
__device__ __forceinline__ void ldsm4(uint32_t& r0, uint32_t& r1, uint32_t& r2, uint32_t& r3,
                                      uint32_t addr) {
    asm volatile("ldmatrix.sync.aligned.m8n8.x4.shared.b16 {%0,%1,%2,%3}, [%4];"
                 : "=r"(r0), "=r"(r1), "=r"(r2), "=r"(r3) : "r"(addr));
}
__device__ __forceinline__ void mma16816(float* c, uint32_t a0, uint32_t a1, uint32_t a2, uint32_t a3,
                                         uint32_t b0, uint32_t b1) {
    asm volatile(
        "mma.sync.aligned.m16n8k16.row.col.f32.bf16.bf16.f32 "
        "{%0,%1,%2,%3}, {%4,%5,%6,%7}, {%8,%9}, {%0,%1,%2,%3};"
        : "+f"(c[0]), "+f"(c[1]), "+f"(c[2]), "+f"(c[3])
        : "r"(a0), "r"(a1), "r"(a2), "r"(a3), "r"(b0), "r"(b1));
}
__device__ __forceinline__ void mma_f16(float* c, uint32_t a0, uint32_t a1, uint32_t a2, uint32_t a3,
                                        uint32_t b0, uint32_t b1) {
    asm volatile(
        "mma.sync.aligned.m16n8k16.row.col.f32.f16.f16.f32 "
        "{%0,%1,%2,%3}, {%4,%5,%6,%7}, {%8,%9}, {%0,%1,%2,%3};"
        : "+f"(c[0]), "+f"(c[1]), "+f"(c[2]), "+f"(c[3])
        : "r"(a0), "r"(a1), "r"(a2), "r"(a3), "r"(b0), "r"(b1));
}

// ============================================================================
// Weight split pre-kernel: build pre-swizzled bf16 hi/lo B-tiles per K-chunk.
// ch 0..31 <- wq (keys), 32..63 <- wk (queries), 64..319 <- wv (values).
// ============================================================================
__global__ void wsplit_kernel(const float* __restrict__ wq, const float* __restrict__ wk,
                              const float* __restrict__ wv, unsigned char* __restrict__ wt) {
    int idx = blockIdx.x * 256 + threadIdx.x;
    if (idx >= 2560) return;
    int ch = idx % 320, cb = idx / 320;      // cb = K-chunk 0..7
    const float* src = (ch < 32) ? (wq + ch * C_IN)
                     : (ch < 64) ? (wk + (ch - 32) * C_IN)
                                 : (wv + (ch - 64) * C_IN);
    unsigned char* base = wt + cb * WT_CHUNK;
#pragma unroll
    for (int c = 0; c < 32; c += 2) {
        uint32_t hi, lo;
        split2(src[cb * 32 + c], src[cb * 32 + c + 1], hi, lo);
        *(uint32_t*)(base + SW((uint32_t)ch * 128 + c * 2))      = hi;
        *(uint32_t*)(base + SW((uint32_t)ch * 128 + 64 + c * 2)) = lo;
    }
}

// ============================================================================
// Tensor-core projection: CTA = 64 positions x 320 channels, 8 warps
// (wm = warp&3 -> m16 tile, wn = warp>>2 -> 160-channel half). bf16 3-term.
// Writes Q/K/V tiles in exactly the formats the attention kernel consumes.
// ============================================================================
__global__ void __launch_bounds__(256, 2)
proj_mma_kernel(const float* __restrict__ x,
                const float* __restrict__ bq, const float* __restrict__ bk,
                const float* __restrict__ bv, const unsigned char* __restrict__ wt,
                unsigned char* __restrict__ ktP, unsigned char* __restrict__ qtP,
                unsigned char* __restrict__ vtP) {
    extern __shared__ __align__(1024) unsigned char sm[];
    const uint32_t sb = smem_u32(sm);
    const int tid = threadIdx.x;
    const int lane = tid & 31, warp = tid >> 5;
    const int wm = warp & 3, wn = warp >> 2;
    const int b = blockIdx.y;
    const int n0 = blockIdx.x * 64;

    const uint32_t OFF_MB[2] = {0, 8};
    const uint32_t OFF_A = 1024;                 // A tile: 64 n-rows x 128B
    const uint32_t OFF_BIAS = 9216;              // 320 f32
    const uint32_t OFF_B[2] = {11264, 52224};    // B tiles: 320 ch-rows x 128B

    if (tid == 0) { mbar_init(sb + OFF_MB[0], 1); mbar_init(sb + OFF_MB[1], 1); }
    for (int i = tid; i < 320; i += 256) {
        float v = (i < 32) ? bq[i] : (i < 64) ? bk[i - 32] : bv[i - 64];
        ((float*)(sm + OFF_BIAS))[i] = v;
    }
    __syncthreads();
    if (tid == 0) {
        mbar_expect(sb + OFF_MB[0], WT_CHUNK);
        bulk_g2s(sb + OFF_B[0], wt, WT_CHUNK, sb + OFF_MB[0]);
        mbar_expect(sb + OFF_MB[1], WT_CHUNK);
        bulk_g2s(sb + OFF_B[1], wt + WT_CHUNK, WT_CHUNK, sb + OFF_MB[1]);
    }

    float acc[20][4];
#pragma unroll
    for (int j = 0; j < 20; j++)
#pragma unroll
        for (int e = 0; e < 4; e++) acc[j][e] = 0.f;

    for (int cb = 0; cb < 8; cb++) {
        __syncthreads();   // prev chunk's MMAs done with A and B[(cb+1)&1]
        if (tid == 0 && cb >= 1 && cb + 1 < 8) {
            const uint32_t mbn = sb + OFF_MB[(cb + 1) & 1];
            mbar_expect(mbn, WT_CHUNK);
            bulk_g2s(sb + OFF_B[(cb + 1) & 1], wt + (cb + 1) * WT_CHUNK, WT_CHUNK, mbn);
        }
        // transpose+split x[32c x 64n] -> A tile [n][c] (coalesced LDG, paired c)
        {
            int c2 = tid >> 4, q = tid & 15;     // c pair c2*2, n quad q*4
            const float* xr = &x[((size_t)b * C_IN + cb * 32 + c2 * 2) * NPOS + n0 + q * 4];
            float4 va = *(const float4*)xr;
            float4 vb = *(const float4*)(xr + NPOS);
            float aa[4] = {va.x, va.y, va.z, va.w};
            float bb[4] = {vb.x, vb.y, vb.z, vb.w};
#pragma unroll
            for (int r = 0; r < 4; r++) {
                uint32_t hi, lo;
                split2(aa[r], bb[r], hi, lo);
                uint32_t off = (uint32_t)(q * 4 + r) * 128 + c2 * 4;
                sts32(sb + OFF_A + SW(off), hi);
                sts32(sb + OFF_A + SW(off + 64), lo);
            }
        }
        mbar_wait(sb + OFF_MB[cb & 1], (cb >> 1) & 1);
        __syncthreads();   // A stores visible

        // A fragments (m16 x k32, hi + lo)
        uint32_t Ah[2][4], Al[2][4];
        {
            uint32_t row = wm * 16 + (lane & 7) + ((lane >> 3) & 1) * 8;
#pragma unroll
            for (int s = 0; s < 2; s++) {
                ldsm4(Ah[s][0], Ah[s][1], Ah[s][2], Ah[s][3],
                      sb + OFF_A + SW(row * 128 + s * 32 + (lane >> 4) * 16));
                ldsm4(Al[s][0], Al[s][1], Al[s][2], Al[s][3],
                      sb + OFF_A + SW(row * 128 + 64 + s * 32 + (lane >> 4) * 16));
            }
        }
        const uint32_t Bbase = sb + OFF_B[cb & 1];
#pragma unroll
        for (int jn = 0; jn < 20; jn++) {
            uint32_t brow = wn * 160 + jn * 8 + (lane & 7);
            uint32_t bcol = (lane >> 3) * 16;
            uint32_t bh[4], bl[4];
            ldsm4(bh[0], bh[1], bh[2], bh[3], Bbase + SW(brow * 128 + bcol));
            ldsm4(bl[0], bl[1], bl[2], bl[3], Bbase + SW(brow * 128 + 64 + bcol));
#pragma unroll
            for (int s = 0; s < 2; s++) {
                mma16816(acc[jn], Ah[s][0], Ah[s][1], Ah[s][2], Ah[s][3], bh[2 * s], bh[2 * s + 1]);
                mma16816(acc[jn], Ah[s][0], Ah[s][1], Ah[s][2], Ah[s][3], bl[2 * s], bl[2 * s + 1]);
                mma16816(acc[jn], Al[s][0], Al[s][1], Al[s][2], Al[s][3], bh[2 * s], bh[2 * s + 1]);
            }
        }
    }

    // epilogue: bias + write tiles
    const float* bias = (const float*)(sm + OFF_BIAS);
    const int g = lane >> 2, t = lane & 3;
#pragma unroll
    for (int jn = 0; jn < 20; jn++) {
        int ch0 = wn * 160 + jn * 8 + t * 2;
        float b0 = bias[ch0], b1 = bias[ch0 + 1];
#pragma unroll
        for (int h = 0; h < 2; h++) {
            int n = n0 + wm * 16 + g + h * 8;
            float a0 = acc[jn][h * 2] + b0;
            float a1 = acc[jn][h * 2 + 1] + b1;
            if (ch0 < 32) {                      // K tile (bf16 hi/lo)
                uint32_t hi, lo;
                split2(a0, a1, hi, lo);
                size_t tb = ((size_t)b * NCHUNK + blockIdx.x) * KT_BYTES;
                uint32_t row = (uint32_t)(n & 63);
                *(uint32_t*)(ktP + tb + SW(row * 128 + ch0 * 2))      = hi;
                *(uint32_t*)(ktP + tb + SW(row * 128 + 64 + ch0 * 2)) = lo;
            } else if (ch0 < 64) {               // Q tile (bf16 hi/lo)
                int c = ch0 - 32;
                uint32_t hi, lo;
                split2(a0, a1, hi, lo);
                size_t tb = ((size_t)b * MBLKS + (n >> 7)) * QT_BYTES;
                uint32_t row = (uint32_t)(n & 127);
                *(uint32_t*)(qtP + tb + SW(row * 128 + c * 2))      = hi;
                *(uint32_t*)(qtP + tb + SW(row * 128 + 64 + c * 2)) = lo;
            } else {                             // V tile (fp16 [c][key])
                int co = ch0 - 64;
                size_t tb = ((size_t)b * NCHUNK + blockIdx.x) * VT_BYTES;
                uint32_t key = (uint32_t)(n & 63);
                *(__half*)(vtP + tb + SW((uint32_t)co * 128 + key * 2))       = __float2half(a0);
                *(__half*)(vtP + tb + SW((uint32_t)(co + 1) * 128 + key * 2)) = __float2half(a1);
            }
        }
    }
}

// ============================================================================
// Attention (unchanged from R9): S bf16 3-term, exp(s-SHIFT) -> fp16 P,
// PV fp16 m16n8k16, pipelined PV(i) + S(i+1). 8 warps: qg=warp>>1, nh=warp&1.
// ============================================================================
__global__ void __launch_bounds__(256, 1)
attn_kernel(const unsigned char* __restrict__ qt, const unsigned char* __restrict__ kt,
            const unsigned char* __restrict__ vt, float* __restrict__ out) {
    extern __shared__ __align__(1024) unsigned char sm[];
    const uint32_t sb = smem_u32(sm);
    const int tid  = threadIdx.x;
    const int lane = tid & 31;
    const int warp = tid >> 5;
    const int qg = warp >> 1, nh = warp & 1;
    const int b = blockIdx.y, mblk = blockIdx.x;
    const int m0 = mblk * BQ;

    const uint32_t OFF_LD[3] = {0, 8, 16};
    const uint32_t OFF_VD[3] = {24, 32, 40};
    const uint32_t OFF_Q = 1024;
    const uint32_t OFF_K[3] = {17408, 25600, 33792};
    const uint32_t OFF_P[2] = {41984, 58368};
    const uint32_t OFF_V[3] = {74752, 107520, 140288};

    if (tid == 0) {
#pragma unroll
        for (int s = 0; s < 3; s++) {
            mbar_init(sb + OFF_LD[s], 1);
            mbar_init(sb + OFF_VD[s], 8);
        }
    }
    {
        const uint4* s = (const uint4*)(qt + (size_t)(b * MBLKS + mblk) * QT_BYTES);
        uint4* d = (uint4*)(sm + OFF_Q);
        for (int i = tid; i < 1024; i += 256) d[i] = s[i];
    }
    __syncthreads();

    if (tid == 0) {
#pragma unroll
        for (int j = 0; j < 2; j++) {
            mbar_expect(sb + OFF_LD[j], KT_BYTES + VT_BYTES);
            bulk_g2s(sb + OFF_K[j], kt + (size_t)(b * NCHUNK + j) * KT_BYTES, KT_BYTES, sb + OFF_LD[j]);
            bulk_g2s(sb + OFF_V[j], vt + (size_t)(b * NCHUNK + j) * VT_BYTES, VT_BYTES, sb + OFF_LD[j]);
        }
    }

    uint32_t Qf[2][2][2][4];
    {
        const int q0b = qg * 32;
#pragma unroll
        for (int mi = 0; mi < 2; mi++)
#pragma unroll
            for (int ks = 0; ks < 2; ks++)
#pragma unroll
                for (int hb = 0; hb < 2; hb++) {
                    uint32_t row = q0b + mi * 16 + (lane & 7) + ((lane >> 3) & 1) * 8;
                    uint32_t off = hb * 64 + ks * 32 + (lane >> 4) * 16;
                    ldsm4(Qf[mi][ks][hb][0], Qf[mi][ks][hb][1], Qf[mi][ks][hb][2], Qf[mi][ks][hb][3],
                          sb + OFF_Q + SW(row * 128 + off));
                }
    }

    float o[2][16][4];
#pragma unroll
    for (int mi = 0; mi < 2; mi++)
#pragma unroll
        for (int n = 0; n < 16; n++)
#pragma unroll
            for (int e = 0; e < 4; e++) o[mi][n][e] = 0.f;
    float lsum[2][2] = {{0.f, 0.f}, {0.f, 0.f}};

    const int g = lane >> 2, t = lane & 3;

#define S_BLOCK(j, kOff, pDst)                                                              \
    {                                                                                       \
        const uint32_t krow = nh * 32 + (j) * 8 + (lane & 7);                               \
        const uint32_t koff = (lane >> 3) * 16;                                             \
        uint32_t kh[4], kl[4];                                                              \
        ldsm4(kh[0], kh[1], kh[2], kh[3], (kOff) + SW(krow * 128 + koff));                  \
        ldsm4(kl[0], kl[1], kl[2], kl[3], (kOff) + SW(krow * 128 + 64 + koff));             \
        float cs[2][4];                                                                     \
        _Pragma("unroll")                                                                   \
        for (int mi = 0; mi < 2; mi++) {                                                    \
            _Pragma("unroll")                                                               \
            for (int e = 0; e < 4; e++) cs[mi][e] = 0.f;                                    \
            _Pragma("unroll")                                                               \
            for (int ks = 0; ks < 2; ks++) {                                                \
                mma16816(cs[mi], Qf[mi][ks][0][0], Qf[mi][ks][0][1], Qf[mi][ks][0][2],      \
                         Qf[mi][ks][0][3], kh[2 * ks], kh[2 * ks + 1]);                     \
                mma16816(cs[mi], Qf[mi][ks][0][0], Qf[mi][ks][0][1], Qf[mi][ks][0][2],      \
                         Qf[mi][ks][0][3], kl[2 * ks], kl[2 * ks + 1]);                     \
                mma16816(cs[mi], Qf[mi][ks][1][0], Qf[mi][ks][1][1], Qf[mi][ks][1][2],      \
                         Qf[mi][ks][1][3], kh[2 * ks], kh[2 * ks + 1]);                     \
            }                                                                               \
        }                                                                                   \
        const uint32_t keyb = (uint32_t)(nh * 64 + (j) * 16 + 4 * t);                       \
        _Pragma("unroll")                                                                   \
        for (int mi = 0; mi < 2; mi++) {                                                    \
            const uint32_t row0 = qg * 32 + mi * 16 + g;                                    \
            float e0 = __expf(cs[mi][0] - SHIFT), e1 = __expf(cs[mi][1] - SHIFT);           \
            float e2 = __expf(cs[mi][2] - SHIFT), e3 = __expf(cs[mi][3] - SHIFT);           \
            lsum[mi][0] += e0 + e1;                                                         \
            lsum[mi][1] += e2 + e3;                                                         \
            __half2 h01 = __floats2half2_rn(e0, e1);                                        \
            __half2 h23 = __floats2half2_rn(e2, e3);                                        \
            sts32((pDst) + SW(row0 * 128 + keyb), *(uint32_t*)&h01);                        \
            sts32((pDst) + SW((row0 + 8) * 128 + keyb), *(uint32_t*)&h23);                  \
        }                                                                                   \
    }

#define PV_BLOCK(ks16, pSrc, vOff)                                                          \
    {                                                                                       \
        uint32_t A[2][4];                                                                   \
        _Pragma("unroll")                                                                   \
        for (int mi = 0; mi < 2; mi++) {                                                    \
            uint32_t row = qg * 32 + mi * 16 + (lane & 7) + ((lane >> 3) & 1) * 8;          \
            ldsm4(A[mi][0], A[mi][1], A[mi][2], A[mi][3],                                   \
                  (pSrc) + SW(row * 128 + (ks16) * 32 + (lane >> 4) * 16));                 \
        }                                                                                   \
        _Pragma("unroll")                                                                   \
        for (int jnp = 0; jnp < 8; jnp++) {                                                 \
            uint32_t vrow = nh * 128 + jnp * 16 + (lane & 7) + ((lane >> 4) & 1) * 8;       \
            uint32_t vcol = (ks16) * 32 + ((lane >> 3) & 1) * 16;                           \
            uint32_t B0, B1, B2, B3;                                                        \
            ldsm4(B0, B1, B2, B3, (vOff) + SW(vrow * 128 + vcol));                          \
            _Pragma("unroll")                                                               \
            for (int mi = 0; mi < 2; mi++) {                                                \
                mma_f16(o[mi][jnp * 2],     A[mi][0], A[mi][1], A[mi][2], A[mi][3], B0, B1);\
                mma_f16(o[mi][jnp * 2 + 1], A[mi][0], A[mi][1], A[mi][2], A[mi][3], B2, B3);\
            }                                                                               \
        }                                                                                   \
    }

    mbar_wait(sb + OFF_LD[0], 0);
    {
        const uint32_t k0 = sb + OFF_K[0], p0 = sb + OFF_P[0];
#pragma unroll
        for (int j = 0; j < 4; j++) S_BLOCK(j, k0, p0)
    }
    barsync(1 + qg);

    for (int ich = 0; ich < NCHUNK - 1; ich++) {
        const uint32_t vOff = sb + OFF_V[ich % 3];
        const uint32_t kOffN = sb + OFF_K[(ich + 1) % 3];
        const uint32_t pCur = sb + OFF_P[ich & 1];
        const uint32_t pNxt = sb + OFF_P[(ich + 1) & 1];

        if (tid == 0) {
            if (ich >= 1) mbar_wait(sb + OFF_VD[(ich - 1) % 3], ((ich - 1) / 3) & 1);
            if (ich + 2 < NCHUNK) {
                const int jn = ich + 2;
                const uint32_t ldn = sb + OFF_LD[jn % 3];
                mbar_expect(ldn, KT_BYTES + VT_BYTES);
                bulk_g2s(sb + OFF_K[jn % 3], kt + (size_t)(b * NCHUNK + jn) * KT_BYTES, KT_BYTES, ldn);
                bulk_g2s(sb + OFF_V[jn % 3], vt + (size_t)(b * NCHUNK + jn) * VT_BYTES, VT_BYTES, ldn);
            }
        }

        PV_BLOCK(0, pCur, vOff)
        mbar_wait(sb + OFF_LD[(ich + 1) % 3], ((ich + 1) / 3) & 1);
        S_BLOCK(0, kOffN, pNxt)
        PV_BLOCK(1, pCur, vOff)
        S_BLOCK(1, kOffN, pNxt)
        PV_BLOCK(2, pCur, vOff)
        S_BLOCK(2, kOffN, pNxt)
        PV_BLOCK(3, pCur, vOff)
        S_BLOCK(3, kOffN, pNxt)

        if (lane == 0) mbar_arrive(sb + OFF_VD[ich % 3]);
        barsync(1 + qg);
    }

    {
        const uint32_t vOff = sb + OFF_V[(NCHUNK - 1) % 3];
        const uint32_t pCur = sb + OFF_P[(NCHUNK - 1) & 1];
#pragma unroll
        for (int ks = 0; ks < 4; ks++) PV_BLOCK(ks, pCur, vOff)
    }

    __syncthreads();
    float* Ls = (float*)(sm + OFF_P[0]);
#pragma unroll
    for (int mi = 0; mi < 2; mi++)
#pragma unroll
        for (int r = 0; r < 2; r++) {
            float v = lsum[mi][r];
            v += __shfl_xor_sync(0xffffffffu, v, 1);
            v += __shfl_xor_sync(0xffffffffu, v, 2);
            if (t == 0) Ls[nh * 128 + qg * 32 + mi * 16 + r * 8 + g] = v;
        }
    __syncthreads();
    float inv[2][2];
#pragma unroll
    for (int mi = 0; mi < 2; mi++)
#pragma unroll
        for (int r = 0; r < 2; r++) {
            int row = qg * 32 + mi * 16 + r * 8 + g;
            inv[mi][r] = 1.0f / (Ls[row] + Ls[128 + row]);
        }

    float* St = (float*)(sm + OFF_V[0]);
#pragma unroll
    for (int mi = 0; mi < 2; mi++) {
        __syncthreads();
#pragma unroll
        for (int n = 0; n < 16; n++) {
            int cb = nh * 128 + n * 8 + 2 * t;
            int s0 = qg * 16 + g;
            St[cb * 68 + s0]           = o[mi][n][0] * inv[mi][0];
            St[(cb + 1) * 68 + s0]     = o[mi][n][1] * inv[mi][0];
            St[cb * 68 + s0 + 8]       = o[mi][n][2] * inv[mi][1];
            St[(cb + 1) * 68 + s0 + 8] = o[mi][n][3] * inv[mi][1];
        }
        __syncthreads();
        for (int i = tid; i < 4096; i += 256) {
            int c = i >> 4, s4 = i & 15;
            float4 v = *(float4*)&St[c * 68 + s4 * 4];
            int q = (s4 >> 2) * 32 + mi * 16 + (s4 & 3) * 4;
            *(float4*)&out[((size_t)b * C_IN + c) * NPOS + m0 + q] = v;
        }
    }
#undef S_BLOCK
#undef PV_BLOCK
}

// ============================================================================
extern "C" void kernel_launch(void* const* d_in, const int* in_sizes, int n_in,
                              void* d_out, int out_size) {
    (void)in_sizes; (void)n_in; (void)out_size;
    const float* x  = (const float*)d_in[0];
    const float* wq = (const float*)d_in[1];
    const float* bq = (const float*)d_in[2];
    const float* wk = (const float*)d_in[3];
    const float* bk = (const float*)d_in[4];
    const float* wv = (const float*)d_in[5];
    const float* bv = (const float*)d_in[6];
    float* out = (float*)d_out;

    unsigned char *qtP, *ktP, *vtP, *wtP;
    cudaGetSymbolAddress((void**)&qtP, g_qt);
    cudaGetSymbolAddress((void**)&ktP, g_kt);
    cudaGetSymbolAddress((void**)&vtP, g_vt);
    cudaGetSymbolAddress((void**)&wtP, g_wt);

    wsplit_kernel<<<10, 256>>>(wq, wk, wv, wtP);

    const int psmem = 93184;
    cudaFuncSetAttribute(proj_mma_kernel, cudaFuncAttributeMaxDynamicSharedMemorySize, psmem);
    proj_mma_kernel<<<dim3(64, NB), 256, psmem>>>(x, bq, bk, bv, wtP, ktP, qtP, vtP);

    const int smem = 173056;
    cudaFuncSetAttribute(attn_kernel, cudaFuncAttributeMaxDynamicSharedMemorySize, smem);
    attn_kernel<<<dim3(MBLKS, NB), 256, smem>>>(qtP, ktP, vtP, out);
}